// round 15
// baseline (speedup 1.0000x reference)
#include <cuda_runtime.h>
#include <cuda_bf16.h>
#include <cuda_fp16.h>
#include <cstdint>

// ---------------------------------------------------------------------------
// EnsembleCausalPredictor: E=4, F=16, O=9, B=512, DIN=32, DH=128, H=4, DK=32
// R13 pipeline (bf16 hi/lo tcgen05 GEMMs) + V/T intermediates stored as fp16
// to cut ~600MB of DRAM traffic.
// ---------------------------------------------------------------------------

#define NE 4
#define NF 16
#define NO 9
#define NB 512
#define NDH 128
#define NFINAL 17
#define NEF (NE*NF)        // 64
#define NCH (NEF*NO)       // 576

#define HBUF (NCH*NB*NDH)
__device__ float g_h1[HBUF];
__device__ float g_h2[HBUF];
__device__ float g_q [HBUF];
__device__ float g_k [HBUF];
__device__ __half g_v [HBUF];
__device__ __half g_t [HBUF];
__device__ float g_po[NEF*NB*NDH];
__device__ float g_p [NEF*NB*NDH];

#if defined(__CUDA_ARCH_FEAT_SM103_ALL) || defined(__CUDA_ARCH_FEAT_SM100_ALL)
#define TC_OK 1
#else
#define TC_OK 0
#endif

// ------------------------------- PTX helpers ------------------------------
__device__ __forceinline__ uint32_t smem_u32(const void* p) {
    uint32_t a;
    asm("{ .reg .u64 tmp; cvta.to.shared.u64 tmp, %1; cvt.u32.u64 %0, tmp; }"
        : "=r"(a) : "l"(p));
    return a;
}

#if TC_OK
__device__ __forceinline__ uint32_t elect_one() {
    uint32_t p;
    asm volatile("{\n\t.reg .pred p;\n\telect.sync _|p, 0xFFFFFFFF;\n\t"
                 "selp.b32 %0, 1, 0, p;\n\t}" : "=r"(p));
    return p;
}
#define TC_ALLOC(sa, n) \
    asm volatile("tcgen05.alloc.cta_group::1.sync.aligned.shared::cta.b32 [%0], %1;" \
                 :: "r"(sa), "r"(n) : "memory")
#define TC_RELINQ() \
    asm volatile("tcgen05.relinquish_alloc_permit.cta_group::1.sync.aligned;")
#define TC_DEALLOC(tm, n) \
    asm volatile("tcgen05.dealloc.cta_group::1.sync.aligned.b32 %0, %1;" :: "r"(tm), "r"(n))
#define MBAR_INIT(a, c) \
    asm volatile("mbarrier.init.shared.b64 [%0], %1;" :: "r"(a), "r"(c) : "memory")
#define MBAR_INVAL(a) \
    asm volatile("mbarrier.inval.shared.b64 [%0];" :: "r"(a) : "memory")
#define TC_COMMIT(a) \
    asm volatile("tcgen05.commit.cta_group::1.mbarrier::arrive::one.shared::cluster.b64 [%0];" \
                 :: "r"(a) : "memory")
#define TC_WAIT_LD()  asm volatile("tcgen05.wait::ld.sync.aligned;" ::: "memory")
#define TC_WAIT_ST()  asm volatile("tcgen05.wait::st.sync.aligned;" ::: "memory")
#define TC_FENCE_AFTER()  asm volatile("tcgen05.fence::after_thread_sync;" ::: "memory")
#define TC_FENCE_BEFORE() asm volatile("tcgen05.fence::before_thread_sync;" ::: "memory")
#define FENCE_ASYNC() asm volatile("fence.proxy.async.shared::cta;" ::: "memory")
#define CP_COMMIT() asm volatile("cp.async.commit_group;" ::: "memory")
#define CP_WAIT1()  asm volatile("cp.async.wait_group 1;" ::: "memory")
#define CP_WAIT0()  asm volatile("cp.async.wait_group 0;" ::: "memory")

__device__ __forceinline__ void mbar_wait(uint32_t a, uint32_t parity) {
    asm volatile(
        "{\n\t.reg .pred P1;\n\t"
        "WAIT_LOOP_%=:\n\t"
        "mbarrier.try_wait.parity.acquire.cta.shared::cta.b64 P1, [%0], %1, 0x989680;\n\t"
        "@P1 bra.uni WAIT_DONE_%=;\n\t"
        "bra.uni WAIT_LOOP_%=;\n\t"
        "WAIT_DONE_%=:\n\t}"
        :: "r"(a), "r"(parity) : "memory");
}

#define TC_LD_X32(r, tm) \
    asm volatile("tcgen05.ld.sync.aligned.32x32b.x32.b32 " \
        "{%0,%1,%2,%3,%4,%5,%6,%7,%8,%9,%10,%11,%12,%13,%14,%15," \
        "%16,%17,%18,%19,%20,%21,%22,%23,%24,%25,%26,%27,%28,%29,%30,%31}, [%32];" \
        : "=r"((r)[0]),"=r"((r)[1]),"=r"((r)[2]),"=r"((r)[3]), \
          "=r"((r)[4]),"=r"((r)[5]),"=r"((r)[6]),"=r"((r)[7]), \
          "=r"((r)[8]),"=r"((r)[9]),"=r"((r)[10]),"=r"((r)[11]), \
          "=r"((r)[12]),"=r"((r)[13]),"=r"((r)[14]),"=r"((r)[15]), \
          "=r"((r)[16]),"=r"((r)[17]),"=r"((r)[18]),"=r"((r)[19]), \
          "=r"((r)[20]),"=r"((r)[21]),"=r"((r)[22]),"=r"((r)[23]), \
          "=r"((r)[24]),"=r"((r)[25]),"=r"((r)[26]),"=r"((r)[27]), \
          "=r"((r)[28]),"=r"((r)[29]),"=r"((r)[30]),"=r"((r)[31]) \
        : "r"(tm))

#define TC_ST_X16(tm, r) \
    asm volatile("tcgen05.st.sync.aligned.32x32b.x16.b32 [%0], " \
        "{%1,%2,%3,%4,%5,%6,%7,%8,%9,%10,%11,%12,%13,%14,%15,%16};" \
        :: "r"(tm), \
           "r"((r)[0]),"r"((r)[1]),"r"((r)[2]),"r"((r)[3]), \
           "r"((r)[4]),"r"((r)[5]),"r"((r)[6]),"r"((r)[7]), \
           "r"((r)[8]),"r"((r)[9]),"r"((r)[10]),"r"((r)[11]), \
           "r"((r)[12]),"r"((r)[13]),"r"((r)[14]),"r"((r)[15]) \
        : "memory")

#define TC_ST_X32(tm, r) \
    asm volatile("tcgen05.st.sync.aligned.32x32b.x32.b32 [%0], " \
        "{%1,%2,%3,%4,%5,%6,%7,%8,%9,%10,%11,%12,%13,%14,%15,%16," \
        "%17,%18,%19,%20,%21,%22,%23,%24,%25,%26,%27,%28,%29,%30,%31,%32};" \
        :: "r"(tm), \
           "r"((r)[0]),"r"((r)[1]),"r"((r)[2]),"r"((r)[3]), \
           "r"((r)[4]),"r"((r)[5]),"r"((r)[6]),"r"((r)[7]), \
           "r"((r)[8]),"r"((r)[9]),"r"((r)[10]),"r"((r)[11]), \
           "r"((r)[12]),"r"((r)[13]),"r"((r)[14]),"r"((r)[15]), \
           "r"((r)[16]),"r"((r)[17]),"r"((r)[18]),"r"((r)[19]), \
           "r"((r)[20]),"r"((r)[21]),"r"((r)[22]),"r"((r)[23]), \
           "r"((r)[24]),"r"((r)[25]),"r"((r)[26]),"r"((r)[27]), \
           "r"((r)[28]),"r"((r)[29]),"r"((r)[30]),"r"((r)[31]) \
        : "memory")

// SMEM descriptor: SW128, version=1, SBO=64, LBO=1
__device__ __forceinline__ uint64_t mk_desc(uint32_t base) {
    const uint64_t B =
        (uint64_t(2) << 61) | (uint64_t(1) << 46) | (uint64_t(64) << 32) | (uint64_t(1) << 16);
    return B | ((uint64_t)(base >> 4) & 0x3FFF);
}

// TS-mode cg1 kind::f16 MMA (A in TMEM, bf16, fp32 acc)
__device__ __forceinline__ void mma_ts(uint32_t d, uint32_t a_tm, uint64_t b,
                                       uint32_t idesc, uint32_t acc) {
    asm volatile(
        "{\n\t.reg .pred p;\n\tsetp.ne.u32 p, %4, 0;\n\t"
        "tcgen05.mma.cta_group::1.kind::f16 [%0], [%1], %2, %3, {%5,%5,%5,%5}, p;\n\t}"
        :: "r"(d), "r"(a_tm), "l"(b), "r"(idesc), "r"(acc), "r"(0u) : "memory");
}
#endif  // TC_OK

// idesc: dtype=F32, atype=BF16, btype=BF16, N=128, M=128
#define IDESC_128 ((1u<<4)|(1u<<7)|(1u<<10)|((128u/8)<<17)|((128u/16)<<24))

// Blocked SW128 atom layout for a [128 rows, K cols] bf16 tile in smem.
__device__ __forceinline__ uint32_t lay128(int r, int c) {
    uint32_t off = ((uint32_t)(c >> 6) * 16u + (uint32_t)(r >> 3)) * 1024u
                 + (uint32_t)(r & 7) * 128u + (uint32_t)(c & 63) * 2u;
    return off ^ ((off >> 3) & 0x70u);
}
__device__ __forceinline__ uint32_t doff(int s) {
    return (uint32_t)(s >> 2) * 1024u + (uint32_t)(s & 3) * 2u;
}

// pack two fp32 -> bf16x2 (a = low element)
__device__ __forceinline__ uint32_t bf2(float a, float b) {
    uint32_t r;
    asm("cvt.rn.bf16x2.f32 %0, %1, %2;" : "=r"(r) : "f"(b), "f"(a));
    return r;
}
__device__ __forceinline__ void split2(float a, float b, uint32_t& hi, uint32_t& lo) {
    hi = bf2(a, b);
    float ra = __uint_as_float(hi << 16);
    float rb = __uint_as_float(hi & 0xFFFF0000u);
    lo = bf2(a - ra, b - rb);
}
// pack two fp32 -> fp16x2 (a = low element)
__device__ __forceinline__ uint32_t f2h2(float a, float b) {
    uint32_t r;
    asm("cvt.rn.f16x2.f32 %0, %1, %2;" : "=r"(r) : "f"(b), "f"(a));
    return r;
}

#if TC_OK
// W conv: fp32 [K,128] -> bf16 hi/lo [N=128,K] blocked SW128 in smem.
template<int K>
__device__ __forceinline__ void conv_w(char* smem, const float* Wb,
                                       int offH, int offL, int t) {
    #pragma unroll 2
    for (int i = t; i < (K / 2) * 32; i += 256) {
        int kp = i >> 5;
        int n4 = (i & 31) * 4;
        float4 v0 = *(const float4*)(Wb + (size_t)(2 * kp) * 128 + n4);
        float4 v1 = *(const float4*)(Wb + (size_t)(2 * kp + 1) * 128 + n4);
        const float* e0 = (const float*)&v0;
        const float* e1 = (const float*)&v1;
        #pragma unroll
        for (int j = 0; j < 4; j++) {
            uint32_t hi, lo;
            split2(e0[j], e1[j], hi, lo);
            uint32_t off = lay128(n4 + j, 2 * kp);
            *(uint32_t*)(smem + offH + off) = hi;
            *(uint32_t*)(smem + offL + off) = lo;
        }
    }
}

// issue 3-plane MMA chain: D = Ah*Wh + Ah*Wl + Al*Wh
template<int K>
__device__ __forceinline__ void mma_chain(uint32_t d, uint32_t tmemA,
                                          uint64_t wh, uint64_t wl) {
    constexpr int NS = K / 16;
    #pragma unroll
    for (int s = 0; s < NS; s++)
        mma_ts(d, tmemA + s * 8, wh + doff(s), IDESC_128, s > 0);
    #pragma unroll
    for (int s = 0; s < NS; s++)
        mma_ts(d, tmemA + s * 8, wl + doff(s), IDESC_128, 1);
    #pragma unroll
    for (int s = 0; s < NS; s++)
        mma_ts(d, tmemA + K / 2 + s * 8, wh + doff(s), IDESC_128, 1);
}
#endif

// ---------------------------------------------------------------------------
// Fused QKV: Q/K fp32 out, V fp16 out.  Grid = 576. 256 threads.
// ---------------------------------------------------------------------------
__global__ void __launch_bounds__(256) qkv_ts(
    const float* __restrict__ X,
    const float* __restrict__ Wq, const float* __restrict__ Wk,
    const float* __restrict__ Wv,
    float* __restrict__ Qo, float* __restrict__ Ko, __half* __restrict__ Vo)
{
    extern __shared__ char smem[];
    const int t = threadIdx.x;
    const int bz = blockIdx.x;
    const float* Ab = X + (size_t)bz * 512 * 128;

#if TC_OK
    constexpr int OFF_STG = 1024;              // 2 x 16KB stage
    constexpr int OFF_W   = OFF_STG + 32768;   // 6 x 32KB (q,k,v hi/lo)
    const uint32_t sb = smem_u32(smem);
    const int wid = t >> 5, lid = t & 31;
    float* stg = (float*)(smem + OFF_STG);

    if (t == 0) { MBAR_INIT(sb + 8, 1); MBAR_INIT(sb + 16, 1); }

    const float* Ws[3] = { Wq + (size_t)bz * 128 * 128,
                           Wk + (size_t)bz * 128 * 128,
                           Wv + (size_t)bz * 128 * 128 };
    #pragma unroll
    for (int w = 0; w < 3; w++)
        conv_w<128>(smem, Ws[w], OFF_W + w * 65536, OFF_W + w * 65536 + 32768, t);

    __syncthreads();
    if (wid == 0) { TC_ALLOC(sb, 512); TC_RELINQ(); }
    __syncthreads();
    uint32_t tmem;
    asm volatile("ld.shared.b32 %0, [%1];" : "=r"(tmem) : "r"(sb));
    const uint32_t D0 = tmem + 128, D1 = tmem + 256;

    uint64_t wdh[3], wdl[3];
    #pragma unroll
    for (int w = 0; w < 3; w++) {
        wdh[w] = mk_desc(sb + OFF_W + w * 65536);
        wdl[w] = mk_desc(sb + OFF_W + w * 65536 + 32768);
    }

    const int sub  = wid & 3;
    const int isLo = wid >> 2;
    const int row  = sub * 32 + lid;
    const int c0   = isLo * 64;

    auto stage_issue = [&](int g) {
        const int tile = g >> 2;
        const int c    = g & 3;
        const float* At = Ab + (size_t)tile * 128 * 128 + c * 32;
        const uint32_t dstb = sb + OFF_STG + (uint32_t)(g & 1) * 16384u;
        #pragma unroll
        for (int i = t; i < 1024; i += 256) {
            int r = i >> 3, j = i & 7;
            const float* src = At + (size_t)r * 128 + j * 4;
            uint32_t dst = dstb + (uint32_t)(r * 32 + (((j + r) & 7) << 2)) * 4u;
            asm volatile("cp.async.cg.shared.global [%0], [%1], 16;"
                         :: "r"(dst), "l"(src));
        }
        CP_COMMIT();
    };
    auto epi = [&](uint32_t dbase, float* outp, int tile) {
        float* cp = outp + (size_t)bz * 512 * 128 + ((size_t)tile * 128 + row) * 128;
        #pragma unroll
        for (int cb = 0; cb < 2; cb++) {
            const int cc = c0 + cb * 32;
            uint32_t r[32];
            TC_LD_X32(r, dbase + cc);
            TC_WAIT_LD();
            #pragma unroll
            for (int q8 = 0; q8 < 8; q8++)
                *(float4*)(cp + cc + q8 * 4) = make_float4(
                    __uint_as_float(r[q8*4+0]), __uint_as_float(r[q8*4+1]),
                    __uint_as_float(r[q8*4+2]), __uint_as_float(r[q8*4+3]));
        }
        TC_FENCE_BEFORE();
    };
    auto epiV = [&](uint32_t dbase, __half* outp, int tile) {
        __half* cp = outp + (size_t)bz * 512 * 128 + ((size_t)tile * 128 + row) * 128;
        #pragma unroll
        for (int cb = 0; cb < 2; cb++) {
            const int cc = c0 + cb * 32;
            uint32_t r[32];
            TC_LD_X32(r, dbase + cc);
            TC_WAIT_LD();
            #pragma unroll
            for (int q8 = 0; q8 < 8; q8++) {
                uint2 hv;
                hv.x = f2h2(__uint_as_float(r[q8*4+0]), __uint_as_float(r[q8*4+1]));
                hv.y = f2h2(__uint_as_float(r[q8*4+2]), __uint_as_float(r[q8*4+3]));
                *(uint2*)(cp + cc + q8 * 4) = hv;
            }
        }
        TC_FENCE_BEFORE();
    };

    stage_issue(0);
    int g = 0, p0 = 0, p1 = 0;

    for (int tile = 0; tile < 4; tile++) {
        #pragma unroll
        for (int c = 0; c < 4; c++, g++) {
            if (g + 1 < 16) { stage_issue(g + 1); CP_WAIT1(); }
            else            { CP_WAIT0(); }
            __syncthreads();
            const float* sbuf = stg + (g & 1) * 4096;
            uint32_t rr[16];
            #pragma unroll
            for (int j = 0; j < 8; j++) {
                float4 v = *(const float4*)(sbuf + row * 32 + (((j + row) & 7) << 2));
                uint32_t h0 = bf2(v.x, v.y);
                uint32_t h1 = bf2(v.z, v.w);
                if (!isLo) { rr[2*j] = h0; rr[2*j+1] = h1; }
                else {
                    float ax = __uint_as_float(h0 << 16);
                    float ay = __uint_as_float(h0 & 0xFFFF0000u);
                    float az = __uint_as_float(h1 << 16);
                    float aw = __uint_as_float(h1 & 0xFFFF0000u);
                    rr[2*j]   = bf2(v.x - ax, v.y - ay);
                    rr[2*j+1] = bf2(v.z - az, v.w - aw);
                }
            }
            TC_ST_X16(tmem + (uint32_t)isLo * 64 + c * 16, rr);
            __syncthreads();
        }
        TC_WAIT_ST();
        TC_FENCE_BEFORE();
        __syncthreads();

        if (wid == 0) {
            FENCE_ASYNC();
            TC_FENCE_AFTER();
            if (elect_one()) {
                mma_chain<128>(D0, tmem, wdh[0], wdl[0]); TC_COMMIT(sb + 8);
                mma_chain<128>(D1, tmem, wdh[1], wdl[1]); TC_COMMIT(sb + 16);
            }
        }

        mbar_wait(sb + 8, p0); p0 ^= 1;
        TC_FENCE_AFTER();
        epi(D0, Qo, tile);
        __syncthreads();
        if (wid == 0) {
            TC_FENCE_AFTER();
            if (elect_one()) { mma_chain<128>(D0, tmem, wdh[2], wdl[2]); TC_COMMIT(sb + 8); }
        }
        mbar_wait(sb + 16, p1); p1 ^= 1;
        TC_FENCE_AFTER();
        epi(D1, Ko, tile);
        mbar_wait(sb + 8, p0); p0 ^= 1;
        TC_FENCE_AFTER();
        epiV(D0, Vo, tile);
        __syncthreads();
    }

    __syncthreads();
    if (t == 0) { MBAR_INVAL(sb + 8); MBAR_INVAL(sb + 16); }
    __syncthreads();
    if (wid == 0) TC_DEALLOC(tmem, 512);
#else
    const float* Wsrc[3] = { Wq + (size_t)bz*128*128, Wk + (size_t)bz*128*128,
                             Wv + (size_t)bz*128*128 };
    for (int w = 0; w < 3; w++)
        for (int i = t; i < 512 * 128; i += 256) {
            int r = i >> 7, c = i & 127;
            float s = 0.f;
            for (int k = 0; k < 128; k++)
                s += Ab[(size_t)r * 128 + k] * Wsrc[w][(size_t)k * 128 + c];
            if (w == 0) Qo[(size_t)bz*512*128 + i] = s;
            else if (w == 1) Ko[(size_t)bz*512*128 + i] = s;
            else Vo[(size_t)bz*512*128 + i] = __float2half(s);
        }
#endif
}

// ---------------------------------------------------------------------------
// Fused 2-stage GEMM (A fp32 or fp16 via AHALF):
//   H = epi1(A@W1 [+b1][relu][+Res]); Out = epi2(H@W2 [+b2][relu])
// TMEM: A[0,128) H[128,256) D0[256,384) D1[384,512).
// ---------------------------------------------------------------------------
template<int K1, bool BIAS1, bool RELU1, bool RES1, bool BIAS2, bool RELU2,
         bool AHALF = false>
__global__ void __launch_bounds__(256) gemm2_ts(
    const void* __restrict__ Av,
    const float* __restrict__ W1, const float* __restrict__ b1,
    const float* __restrict__ Res,
    const float* __restrict__ W2, const float* __restrict__ b2,
    float* __restrict__ Out)
{
    extern __shared__ char smem[];
    const int t = threadIdx.x;
    const int bz = blockIdx.x;
    const float* Rb = RES1 ? Res + (size_t)bz * 512 * 128 : nullptr;
    float*       Ob = Out + (size_t)bz * 512 * 128;

#if TC_OK
    constexpr int W1BYTES = (K1 >= 128) ? 32768 : 16384;
    constexpr int OFF_STG = 2048;
    constexpr int OFF_W1H = OFF_STG + 32768;
    constexpr int OFF_W1L = OFF_W1H + W1BYTES;
    constexpr int OFF_W2H = OFF_W1L + W1BYTES;
    constexpr int OFF_W2L = OFF_W2H + 32768;
    constexpr int NCHK1 = K1 / 32;
    constexpr int NG = 4 * NCHK1;

    const uint32_t sb = smem_u32(smem);
    const int wid = t >> 5, lid = t & 31;
    float* bias1_s = (float*)(smem + 64);
    float* bias2_s = (float*)(smem + 576);
    float* stg = (float*)(smem + OFF_STG);

    if (t == 0) { MBAR_INIT(sb + 8, 1); MBAR_INIT(sb + 16, 1); }

    conv_w<K1 >(smem, W1 + (size_t)bz * K1 * 128, OFF_W1H, OFF_W1L, t);
    conv_w<128>(smem, W2 + (size_t)bz * 128 * 128, OFF_W2H, OFF_W2L, t);
    if (BIAS1 && t < 128) bias1_s[t] = b1[(size_t)bz * 128 + t];
    if (BIAS2 && t < 128) bias2_s[t] = b2[(size_t)bz * 128 + t];

    __syncthreads();
    if (wid == 0) { TC_ALLOC(sb, 512); TC_RELINQ(); }
    __syncthreads();
    uint32_t tmem;
    asm volatile("ld.shared.b32 %0, [%1];" : "=r"(tmem) : "r"(sb));
    const uint32_t TM_A = tmem;
    const uint32_t TM_H = tmem + 128;
    const uint32_t D0   = tmem + 256;
    const uint32_t D1   = tmem + 384;

    const uint64_t w1h = mk_desc(sb + OFF_W1H), w1l = mk_desc(sb + OFF_W1L);
    const uint64_t w2h = mk_desc(sb + OFF_W2H), w2l = mk_desc(sb + OFF_W2L);

    const int sub  = wid & 3;
    const int isLo = wid >> 2;
    const int row  = sub * 32 + lid;
    const int ch   = isLo;
    const int c0   = ch * 64;

    int g = 0;

    auto stage_issue = [&](int gg) {
        const int tile = gg / NCHK1;
        const int c    = gg - tile * NCHK1;
        if (AHALF) {
            const __half* At = (const __half*)Av
                + (size_t)bz * 512 * K1 + (size_t)tile * 128 * K1 + c * 32;
            const uint32_t dstb = sb + OFF_STG + (uint32_t)(gg & 1) * 8192u;
            #pragma unroll
            for (int i = t; i < 512; i += 256) {
                int r = i >> 2, j = i & 3;
                const __half* src = At + (size_t)r * K1 + j * 8;
                uint32_t dst = dstb + (uint32_t)(r * 64 + (((j + r) & 3) << 4));
                asm volatile("cp.async.cg.shared.global [%0], [%1], 16;"
                             :: "r"(dst), "l"(src));
            }
        } else {
            const float* At = (const float*)Av
                + (size_t)bz * 512 * K1 + (size_t)tile * 128 * K1 + c * 32;
            const uint32_t dstb = sb + OFF_STG + (uint32_t)(gg & 1) * 16384u;
            #pragma unroll
            for (int i = t; i < 1024; i += 256) {
                int r = i >> 3, j = i & 7;
                const float* src = At + (size_t)r * K1 + j * 4;
                uint32_t dst = dstb + (uint32_t)(r * 32 + (((j + r) & 7) << 2)) * 4u;
                asm volatile("cp.async.cg.shared.global [%0], [%1], 16;"
                             :: "r"(dst), "l"(src));
            }
        }
        CP_COMMIT();
    };

    auto convA = [&]() {
        #pragma unroll
        for (int c = 0; c < NCHK1; c++, g++) {
            if (g + 1 < NG) { stage_issue(g + 1); CP_WAIT1(); }
            else            { CP_WAIT0(); }
            __syncthreads();
            uint32_t rr[16];
            if (AHALF) {
                const char* sbuf = (const char*)stg + (g & 1) * 8192;
                #pragma unroll
                for (int j = 0; j < 4; j++) {
                    uint4 hv = *(const uint4*)(sbuf + row * 64 + (((j + row) & 3) << 4));
                    const uint32_t* hw = (const uint32_t*)&hv;
                    #pragma unroll
                    for (int m = 0; m < 4; m++) {
                        __half2 p = *(const __half2*)&hw[m];
                        float2 f = __half22float2(p);
                        uint32_t hi, lo;
                        split2(f.x, f.y, hi, lo);
                        rr[j * 4 + m] = isLo ? lo : hi;
                    }
                }
            } else {
                const float* sbuf = stg + (g & 1) * 4096;
                #pragma unroll
                for (int j = 0; j < 8; j++) {
                    float4 v = *(const float4*)(sbuf + row * 32 + (((j + row) & 7) << 2));
                    uint32_t h0 = bf2(v.x, v.y);
                    uint32_t h1 = bf2(v.z, v.w);
                    if (!isLo) { rr[2*j] = h0; rr[2*j+1] = h1; }
                    else {
                        float ax = __uint_as_float(h0 << 16);
                        float ay = __uint_as_float(h0 & 0xFFFF0000u);
                        float az = __uint_as_float(h1 << 16);
                        float aw = __uint_as_float(h1 & 0xFFFF0000u);
                        rr[2*j]   = bf2(v.x - ax, v.y - ay);
                        rr[2*j+1] = bf2(v.z - az, v.w - aw);
                    }
                }
            }
            TC_ST_X16(TM_A + (uint32_t)isLo * (K1 / 2) + c * 16, rr);
            __syncthreads();
        }
        TC_WAIT_ST();
        TC_FENCE_BEFORE();
        __syncthreads();
    };

    // prologue: conv A(0), issue MMA1(0)
    stage_issue(0);
    convA();
    if (wid == 0) {
        FENCE_ASYNC();
        TC_FENCE_AFTER();
        if (elect_one()) { mma_chain<K1>(D0, TM_A, w1h, w1l); TC_COMMIT(sb + 8); }
    }

    int p0 = 0, p1 = 0;

    for (int tile = 0; tile < 4; tile++) {
        // ---- wait MMA1(tile); epi1: D0 (+res/b1/relu) -> bf16 hi/lo -> TM_H ----
        mbar_wait(sb + 8, p0); p0 ^= 1;
        TC_FENCE_AFTER();
        {
            float d[64];
            #pragma unroll
            for (int cb = 0; cb < 2; cb++) {
                uint32_t r[32];
                TC_LD_X32(r, D0 + c0 + cb * 32);
                TC_WAIT_LD();
                #pragma unroll
                for (int q = 0; q < 32; q++) d[cb * 32 + q] = __uint_as_float(r[q]);
            }
            if (RES1) {
                const float* rp = Rb + ((size_t)tile * 128 + row) * 128 + c0;
                #pragma unroll
                for (int q4 = 0; q4 < 16; q4++) {
                    float4 rv = *(const float4*)(rp + q4 * 4);
                    d[q4*4+0] += rv.x; d[q4*4+1] += rv.y;
                    d[q4*4+2] += rv.z; d[q4*4+3] += rv.w;
                }
            }
            if (BIAS1) {
                #pragma unroll
                for (int q = 0; q < 64; q++) d[q] += bias1_s[c0 + q];
            }
            if (RELU1) {
                #pragma unroll
                for (int q = 0; q < 64; q++) d[q] = fmaxf(d[q], 0.f);
            }
            uint32_t hi[32], lo[32];
            #pragma unroll
            for (int j = 0; j < 32; j++) split2(d[2*j], d[2*j+1], hi[j], lo[j]);
            TC_ST_X32(TM_H + ch * 32, hi);
            TC_ST_X32(TM_H + 64 + ch * 32, lo);
            TC_WAIT_ST();
            TC_FENCE_BEFORE();
        }
        __syncthreads();

        // ---- issue MMA2(tile) -> D1 ----
        if (wid == 0) {
            TC_FENCE_AFTER();
            if (elect_one()) { mma_chain<128>(D1, TM_H, w2h, w2l); TC_COMMIT(sb + 16); }
        }

        // ---- overlap: conv A(tile+1) + issue MMA1(tile+1) while MMA2 runs ----
        if (tile + 1 < 4) {
            convA();
            if (wid == 0) {
                FENCE_ASYNC();
                TC_FENCE_AFTER();
                if (elect_one()) { mma_chain<K1>(D0, TM_A, w1h, w1l); TC_COMMIT(sb + 8); }
            }
        }

        // ---- wait MMA2(tile); epi2 -> Out ----
        mbar_wait(sb + 16, p1); p1 ^= 1;
        TC_FENCE_AFTER();
        {
            float* cp = Ob + ((size_t)tile * 128 + row) * 128;
            #pragma unroll
            for (int cb = 0; cb < 2; cb++) {
                const int cc = c0 + cb * 32;
                uint32_t r[32];
                TC_LD_X32(r, D1 + cc);
                TC_WAIT_LD();
                #pragma unroll
                for (int q8 = 0; q8 < 8; q8++) {
                    float4 v = make_float4(
                        __uint_as_float(r[q8*4+0]), __uint_as_float(r[q8*4+1]),
                        __uint_as_float(r[q8*4+2]), __uint_as_float(r[q8*4+3]));
                    if (BIAS2) {
                        v.x += bias2_s[cc + q8*4+0]; v.y += bias2_s[cc + q8*4+1];
                        v.z += bias2_s[cc + q8*4+2]; v.w += bias2_s[cc + q8*4+3];
                    }
                    if (RELU2) {
                        v.x = fmaxf(v.x, 0.f); v.y = fmaxf(v.y, 0.f);
                        v.z = fmaxf(v.z, 0.f); v.w = fmaxf(v.w, 0.f);
                    }
                    *(float4*)(cp + cc + q8 * 4) = v;
                }
            }
            TC_FENCE_BEFORE();
        }
    }

    __syncthreads();
    if (t == 0) { MBAR_INVAL(sb + 8); MBAR_INVAL(sb + 16); }
    __syncthreads();
    if (wid == 0) TC_DEALLOC(tmem, 512);
#else
    float* Hs = (float*)(smem + 2048);   // 128 x 132
    const float* W1b = W1 + (size_t)bz * K1 * 128;
    const float* W2b = W2 + (size_t)bz * 128 * 128;
    for (int tile = 0; tile < 4; tile++) {
        for (int i = t; i < 128 * 128; i += 256) {
            int r = i >> 7, c = i & 127;
            float s = 0.f;
            for (int k = 0; k < K1; k++) {
                float av = AHALF
                    ? __half2float(((const __half*)Av)[(size_t)bz*512*K1
                        + ((size_t)tile*128 + r) * K1 + k])
                    : ((const float*)Av)[(size_t)bz*512*K1
                        + ((size_t)tile*128 + r) * K1 + k];
                s += av * W1b[(size_t)k * 128 + c];
            }
            if (BIAS1) s += b1[(size_t)bz * 128 + c];
            if (RES1)  s += Rb[((size_t)tile * 128 + r) * 128 + c];
            if (RELU1) s = fmaxf(s, 0.f);
            Hs[r * 132 + c] = s;
        }
        __syncthreads();
        for (int i = t; i < 128 * 128; i += 256) {
            int r = i >> 7, c = i & 127;
            float s = 0.f;
            for (int k = 0; k < 128; k++)
                s += Hs[r * 132 + k] * W2b[(size_t)k * 128 + c];
            if (BIAS2) s += b2[(size_t)bz * 128 + c];
            if (RELU2) s = fmaxf(s, 0.f);
            Ob[((size_t)tile * 128 + r) * 128 + c] = s;
        }
        __syncthreads();
    }
#endif
}

// ---------------------------------------------------------------------------
// Single GEMM (predictor): C = relu(A@W + b). Grid = 64.
// ---------------------------------------------------------------------------
template<int K, bool RELU, bool BIAS, bool RES>
__global__ void __launch_bounds__(256) gemm_ts(
    const float* __restrict__ A,
    const float* __restrict__ W,
    const float* __restrict__ bias,
    const float* __restrict__ Res,
    float* __restrict__ C)
{
    extern __shared__ char smem[];
    const int t = threadIdx.x;
    const int bz = blockIdx.x;
    const float* Ab = A + (size_t)bz * 512 * K;
    const float* Wb = W + (size_t)bz * K * 128;
    float*       Cb = C + (size_t)bz * 512 * 128;
    const float* Rb = RES ? Res + (size_t)bz * 512 * 128 : nullptr;

#if TC_OK
    constexpr int WBYTES  = 1024 * 16 * ((K >= 128) ? 2 : 1);
    constexpr int OFF_STG = 1024;
    constexpr int OFF_WH  = OFF_STG + 32768;
    constexpr int OFF_WL  = OFF_WH + WBYTES;
    constexpr int NCHK = K / 32;
    constexpr int NG   = 4 * NCHK;

    const uint32_t sb = smem_u32(smem);
    const int wid = t >> 5, lid = t & 31;
    float* bias_s = (float*)(smem + 32);
    float* stg    = (float*)(smem + OFF_STG);

    if (t == 0) MBAR_INIT(sb + 8, 1);
    conv_w<K>(smem, Wb, OFF_WH, OFF_WL, t);
    if (BIAS && t < 128) bias_s[t] = bias[(size_t)bz * 128 + t];
    __syncthreads();
    if (wid == 0) { TC_ALLOC(sb, 256); TC_RELINQ(); }
    __syncthreads();
    uint32_t tmem;
    asm volatile("ld.shared.b32 %0, [%1];" : "=r"(tmem) : "r"(sb));

    const uint64_t whd = mk_desc(sb + OFF_WH);
    const uint64_t wld = mk_desc(sb + OFF_WL);
    const int sub  = wid & 3;
    const int isLo = wid >> 2;
    const int row  = sub * 32 + lid;

    auto stage_issue = [&](int g) {
        const int tile = g / NCHK;
        const int c    = g - tile * NCHK;
        const float* At = Ab + (size_t)tile * 128 * K + c * 32;
        const uint32_t dstb = sb + OFF_STG + (uint32_t)(g & 1) * 16384u;
        #pragma unroll
        for (int i = t; i < 1024; i += 256) {
            int r = i >> 3, j = i & 7;
            const float* src = At + (size_t)r * K + j * 4;
            uint32_t dst = dstb + (uint32_t)(r * 32 + (((j + r) & 7) << 2)) * 4u;
            asm volatile("cp.async.cg.shared.global [%0], [%1], 16;"
                         :: "r"(dst), "l"(src));
        }
        CP_COMMIT();
    };

    stage_issue(0);
    int g = 0, parity = 0;
    for (int tile = 0; tile < 4; tile++) {
        #pragma unroll
        for (int c = 0; c < NCHK; c++, g++) {
            if (g + 1 < NG) { stage_issue(g + 1); CP_WAIT1(); }
            else            { CP_WAIT0(); }
            __syncthreads();
            const float* sbuf = stg + (g & 1) * 4096;
            uint32_t rr[16];
            #pragma unroll
            for (int j = 0; j < 8; j++) {
                float4 v = *(const float4*)(sbuf + row * 32 + (((j + row) & 7) << 2));
                uint32_t h0 = bf2(v.x, v.y);
                uint32_t h1 = bf2(v.z, v.w);
                if (!isLo) { rr[2*j] = h0; rr[2*j+1] = h1; }
                else {
                    float ax = __uint_as_float(h0 << 16);
                    float ay = __uint_as_float(h0 & 0xFFFF0000u);
                    float az = __uint_as_float(h1 << 16);
                    float aw = __uint_as_float(h1 & 0xFFFF0000u);
                    rr[2*j]   = bf2(v.x - ax, v.y - ay);
                    rr[2*j+1] = bf2(v.z - az, v.w - aw);
                }
            }
            TC_ST_X16(tmem + (uint32_t)isLo * (K / 2) + c * 16, rr);
            __syncthreads();
        }
        TC_WAIT_ST();
        TC_FENCE_BEFORE();
        __syncthreads();
        if (wid == 0) {
            FENCE_ASYNC();
            TC_FENCE_AFTER();
            if (elect_one()) { mma_chain<K>(tmem + 128, tmem, whd, wld); TC_COMMIT(sb + 8); }
        }
        mbar_wait(sb + 8, parity); parity ^= 1;
        TC_FENCE_AFTER();
        {
            float* cp = Cb + ((size_t)tile * 128 + row) * 128;
            const float* rp = RES ? (Rb + ((size_t)tile * 128 + row) * 128) : nullptr;
            const int c0 = isLo * 64;
            #pragma unroll
            for (int cb = 0; cb < 2; cb++) {
                const int cc = c0 + cb * 32;
                uint32_t r[32];
                TC_LD_X32(r, tmem + 128 + cc);
                TC_WAIT_LD();
                #pragma unroll
                for (int q8 = 0; q8 < 8; q8++) {
                    float4 v = make_float4(
                        __uint_as_float(r[q8*4+0]), __uint_as_float(r[q8*4+1]),
                        __uint_as_float(r[q8*4+2]), __uint_as_float(r[q8*4+3]));
                    if (BIAS) {
                        v.x += bias_s[cc+q8*4+0]; v.y += bias_s[cc+q8*4+1];
                        v.z += bias_s[cc+q8*4+2]; v.w += bias_s[cc+q8*4+3];
                    }
                    if (RES) {
                        float4 rv = *(const float4*)(rp + cc + q8 * 4);
                        v.x += rv.x; v.y += rv.y; v.z += rv.z; v.w += rv.w;
                    }
                    if (RELU) {
                        v.x = fmaxf(v.x, 0.f); v.y = fmaxf(v.y, 0.f);
                        v.z = fmaxf(v.z, 0.f); v.w = fmaxf(v.w, 0.f);
                    }
                    *(float4*)(cp + cc + q8 * 4) = v;
                }
            }
            TC_FENCE_BEFORE();
        }
    }
    __syncthreads();
    if (t == 0) MBAR_INVAL(sb + 8);
    __syncthreads();
    if (wid == 0) TC_DEALLOC(tmem, 256);
#else
    for (int i = t; i < 512 * 128; i += 256) {
        int r = i >> 7, c = i & 127;
        float s = 0.f;
        for (int k = 0; k < K; k++)
            s += Ab[(size_t)r * K + k] * Wb[(size_t)k * 128 + c];
        if (BIAS) s += bias[(size_t)bz * 128 + c];
        if (RES)  s += Rb[(size_t)r * 128 + c];
        if (RELU) s = fmaxf(s, 0.f);
        Cb[(size_t)r * 128 + c] = s;
    }
#endif
}

// ---------------------------------------------------------------------------
// Attention core: Q,K fp32; V fp16 in; T fp16 out. 256 threads, 2 batches.
// ---------------------------------------------------------------------------
__global__ void __launch_bounds__(256) attn_kernel(
    const float* __restrict__ Q, const float* __restrict__ Kk,
    const __half* __restrict__ V, __half* __restrict__ T)
{
    const int blk = blockIdx.x;
    const int ef  = blk >> 8;
    const int bp  = (blk & 255) << 1;

    __shared__ float qs[2][NO][132];
    __shared__ float ks[2][NO][132];
    __shared__ float vs[2][NO][132];
    __shared__ float lg[2][4][NO][12];

    const int t  = threadIdx.x;
    const int g  = t >> 7;
    const int tl = t & 127;
    const int b  = bp + g;

    for (int idx = tl; idx < NO * 32; idx += 128) {
        int o  = idx >> 5;
        int c4 = (idx & 31) * 4;
        size_t ga = ((size_t)(ef * NO + o) * NB + b) * 128 + c4;
        *(float4*)&qs[g][o][c4] = *(const float4*)(Q + ga);
        *(float4*)&ks[g][o][c4] = *(const float4*)(Kk + ga);
        uint2 rv = *(const uint2*)(V + ga);
        float2 f0 = __half22float2(*(const __half2*)&rv.x);
        float2 f1 = __half22float2(*(const __half2*)&rv.y);
        vs[g][o][c4 + 0] = f0.x; vs[g][o][c4 + 1] = f0.y;
        vs[g][o][c4 + 2] = f1.x; vs[g][o][c4 + 3] = f1.y;
    }
    __syncthreads();

    const float scale = 0.17677669529663687f;
    for (int e = tl; e < 4 * NO * NO; e += 128) {
        int h   = e / (NO * NO);
        int rem = e - h * NO * NO;
        int i   = rem / NO;
        int j   = rem - i * NO;
        float s = 0.f;
        #pragma unroll
        for (int d = 0; d < 32; d++) s += qs[g][i][h * 32 + d] * ks[g][j][h * 32 + d];
        lg[g][h][i][j] = s * scale;
    }
    __syncthreads();

    if (tl < 4 * NO) {
        int h = tl / NO, i = tl - (tl / NO) * NO;
        float mx = -1e30f;
        #pragma unroll
        for (int j = 0; j < NO; j++) mx = fmaxf(mx, lg[g][h][i][j]);
        float ex[NO]; float s = 0.f;
        #pragma unroll
        for (int j = 0; j < NO; j++) { ex[j] = __expf(lg[g][h][i][j] - mx); s += ex[j]; }
        float inv = 1.f / s;
        #pragma unroll
        for (int j = 0; j < NO; j++) lg[g][h][i][j] = ex[j] * inv;
    }
    __syncthreads();

    const int c = tl, h = c >> 5;
    #pragma unroll
    for (int i = 0; i < NO; i++) {
        float s = 0.f;
        #pragma unroll
        for (int j = 0; j < NO; j++) s += lg[g][h][i][j] * vs[g][j][c];
        T[((size_t)(ef * NO + i) * NB + b) * 128 + c] = __float2half(s);
    }
}

__global__ void __launch_bounds__(256) pool_kernel(
    const float* __restrict__ Hin, float* __restrict__ P)
{
    int idx = blockIdx.x * 256 + threadIdx.x;
    if (idx >= NEF * NB * NDH) return;
    int c = idx & 127, b = (idx >> 7) & 511, ef = idx >> 16;
    float s = 0.f;
    #pragma unroll
    for (int o = 0; o < NO; o++)
        s += Hin[((size_t)(ef * NO + o) * NB + b) * 128 + c];
    P[idx] = s * (1.f / 9.f);
}

__global__ void __launch_bounds__(256) final_kernel(
    const float* __restrict__ A, const float* __restrict__ W,
    const float* __restrict__ bias, float* __restrict__ Out)
{
    const int mt = blockIdx.x;
    const int ef = blockIdx.y;
    __shared__ float As[32][128];
    __shared__ float Ws[128][NFINAL];
    __shared__ float bs[NFINAL];
    const int t = threadIdx.x;
    const float* Ab = A + ((size_t)ef * NB + mt * 32) * 128;
    for (int i = t; i < 32 * 128 / 4; i += 256)
        ((float4*)&As[0][0])[i] = ((const float4*)Ab)[i];
    for (int i = t; i < 128 * NFINAL; i += 256)
        Ws[i / NFINAL][i % NFINAL] = W[(size_t)ef * 128 * NFINAL + i];
    if (t < NFINAL) bs[t] = bias[ef * NFINAL + t];
    __syncthreads();
    for (int idx = t; idx < 32 * NFINAL; idx += 256) {
        int r = idx / NFINAL, j = idx - r * NFINAL;
        float s = bs[j];
        #pragma unroll 16
        for (int k = 0; k < 128; k++) s += As[r][k] * Ws[k][j];
        Out[((size_t)ef * NB + mt * 32 + r) * NFINAL + j] = s;
    }
}

// ---------------------------------------------------------------------------
extern "C" void kernel_launch(void* const* d_in, const int* in_sizes, int n_in,
                              void* d_out, int out_size)
{
    const float* x   = (const float*)d_in[0];
    const float* fw1 = (const float*)d_in[1];
    const float* fb1 = (const float*)d_in[2];
    const float* fw2 = (const float*)d_in[3];
    const float* fb2 = (const float*)d_in[4];
    const float* aw[2][5];
    const float* apb[2];
    for (int i = 0; i < 2; i++) {
        for (int n = 0; n < 5; n++) aw[i][n] = (const float*)d_in[5 + i * 6 + n];
        apb[i] = (const float*)d_in[5 + i * 6 + 5];
    }
    const float* pw1 = (const float*)d_in[17];
    const float* pb1 = (const float*)d_in[18];
    const float* pw2 = (const float*)d_in[19];
    const float* pb2 = (const float*)d_in[20];
    float* out = (float*)d_out;

    float *H1, *H2, *Q, *K, *PO, *P;
    __half *V, *T;
    cudaGetSymbolAddress((void**)&H1, g_h1);
    cudaGetSymbolAddress((void**)&H2, g_h2);
    cudaGetSymbolAddress((void**)&Q,  g_q);
    cudaGetSymbolAddress((void**)&K,  g_k);
    cudaGetSymbolAddress((void**)&V,  g_v);
    cudaGetSymbolAddress((void**)&T,  g_t);
    cudaGetSymbolAddress((void**)&PO, g_po);
    cudaGetSymbolAddress((void**)&P,  g_p);

    const int SMQKV = 1024 + 32768 + 6 * 32768;             // 230,400
    const int SMF12 = 2048 + 32768 + 2 * 16384 + 2 * 32768; // 133,120
    const int SMWP  = 2048 + 32768 + 4 * 32768;             // 165,888
    const int SMPRD = 1024 + 32768 + 2 * 32768;             // 99,328

    cudaFuncSetAttribute(qkv_ts, cudaFuncAttributeMaxDynamicSharedMemorySize, SMQKV);
    cudaFuncSetAttribute(gemm2_ts<32,  true,  true,  false, true, true, false>,
                         cudaFuncAttributeMaxDynamicSharedMemorySize, SMF12);
    cudaFuncSetAttribute(gemm2_ts<128, false, false, true,  true, true, true>,
                         cudaFuncAttributeMaxDynamicSharedMemorySize, SMWP);
    cudaFuncSetAttribute(gemm_ts<128, true, true, false>,
                         cudaFuncAttributeMaxDynamicSharedMemorySize, SMPRD);

    // fused feature_fc (fc1 + fc2): x -> H2
    gemm2_ts<32, true, true, false, true, true, false><<<NCH, 256, SMF12>>>(
        x, fw1, fb1, nullptr, fw2, fb2, H2);

    // two ChannelMHA blocks
    const float* X = H2;
    float* Y = H1;
    for (int a = 0; a < 2; a++) {
        qkv_ts<<<NCH, 256, SMQKV>>>(X, aw[a][0], aw[a][1], aw[a][2], Q, K, V);
        attn_kernel<<<NEF * NB / 2, 256>>>(Q, K, V, T);
        // fused: Y = relu((T@wo + X) @ pw + pb), T stored fp16
        gemm2_ts<128, false, false, true, true, true, true><<<NCH, 256, SMWP>>>(
            T, aw[a][3], nullptr, X, aw[a][4], apb[a], Y);
        const float* nX = Y;
        Y = (a == 0) ? H2 : H1;
        X = nX;
    }
    // X == H2 after the loop

    pool_kernel<<<(NEF * NB * NDH + 255) / 256, 256>>>(X, PO);
    gemm_ts<128, true, true, false><<<NEF, 256, SMPRD>>>(PO, pw1, pb1, nullptr, P);
    final_kernel<<<dim3(16, NEF), 256>>>(P, pw2, pb2, out);
}

// round 16
// speedup vs baseline: 1.0665x; 1.0665x over previous
#include <cuda_runtime.h>
#include <cuda_bf16.h>
#include <cuda_fp16.h>
#include <cstdint>

// ---------------------------------------------------------------------------
// EnsembleCausalPredictor: E=4, F=16, O=9, B=512, DIN=32, DH=128, H=4, DK=32
// All intermediates (H, Q, K, V, T) stored fp16 in gmem; all GEMM math stays
// bf16 hi/lo on tcgen05 with fp32 accumulate.
// ---------------------------------------------------------------------------

#define NE 4
#define NF 16
#define NO 9
#define NB 512
#define NDH 128
#define NFINAL 17
#define NEF (NE*NF)        // 64
#define NCH (NEF*NO)       // 576

#define HBUF (NCH*NB*NDH)
__device__ __half g_h1[HBUF];
__device__ __half g_h2[HBUF];
__device__ __half g_q [HBUF];
__device__ __half g_k [HBUF];
__device__ __half g_v [HBUF];
__device__ __half g_t [HBUF];
__device__ float g_po[NEF*NB*NDH];
__device__ float g_p [NEF*NB*NDH];

#if defined(__CUDA_ARCH_FEAT_SM103_ALL) || defined(__CUDA_ARCH_FEAT_SM100_ALL)
#define TC_OK 1
#else
#define TC_OK 0
#endif

// ------------------------------- PTX helpers ------------------------------
__device__ __forceinline__ uint32_t smem_u32(const void* p) {
    uint32_t a;
    asm("{ .reg .u64 tmp; cvta.to.shared.u64 tmp, %1; cvt.u32.u64 %0, tmp; }"
        : "=r"(a) : "l"(p));
    return a;
}

#if TC_OK
__device__ __forceinline__ uint32_t elect_one() {
    uint32_t p;
    asm volatile("{\n\t.reg .pred p;\n\telect.sync _|p, 0xFFFFFFFF;\n\t"
                 "selp.b32 %0, 1, 0, p;\n\t}" : "=r"(p));
    return p;
}
#define TC_ALLOC(sa, n) \
    asm volatile("tcgen05.alloc.cta_group::1.sync.aligned.shared::cta.b32 [%0], %1;" \
                 :: "r"(sa), "r"(n) : "memory")
#define TC_RELINQ() \
    asm volatile("tcgen05.relinquish_alloc_permit.cta_group::1.sync.aligned;")
#define TC_DEALLOC(tm, n) \
    asm volatile("tcgen05.dealloc.cta_group::1.sync.aligned.b32 %0, %1;" :: "r"(tm), "r"(n))
#define MBAR_INIT(a, c) \
    asm volatile("mbarrier.init.shared.b64 [%0], %1;" :: "r"(a), "r"(c) : "memory")
#define MBAR_INVAL(a) \
    asm volatile("mbarrier.inval.shared.b64 [%0];" :: "r"(a) : "memory")
#define TC_COMMIT(a) \
    asm volatile("tcgen05.commit.cta_group::1.mbarrier::arrive::one.shared::cluster.b64 [%0];" \
                 :: "r"(a) : "memory")
#define TC_WAIT_LD()  asm volatile("tcgen05.wait::ld.sync.aligned;" ::: "memory")
#define TC_WAIT_ST()  asm volatile("tcgen05.wait::st.sync.aligned;" ::: "memory")
#define TC_FENCE_AFTER()  asm volatile("tcgen05.fence::after_thread_sync;" ::: "memory")
#define TC_FENCE_BEFORE() asm volatile("tcgen05.fence::before_thread_sync;" ::: "memory")
#define FENCE_ASYNC() asm volatile("fence.proxy.async.shared::cta;" ::: "memory")
#define CP_COMMIT() asm volatile("cp.async.commit_group;" ::: "memory")
#define CP_WAIT1()  asm volatile("cp.async.wait_group 1;" ::: "memory")
#define CP_WAIT0()  asm volatile("cp.async.wait_group 0;" ::: "memory")

__device__ __forceinline__ void mbar_wait(uint32_t a, uint32_t parity) {
    asm volatile(
        "{\n\t.reg .pred P1;\n\t"
        "WAIT_LOOP_%=:\n\t"
        "mbarrier.try_wait.parity.acquire.cta.shared::cta.b64 P1, [%0], %1, 0x989680;\n\t"
        "@P1 bra.uni WAIT_DONE_%=;\n\t"
        "bra.uni WAIT_LOOP_%=;\n\t"
        "WAIT_DONE_%=:\n\t}"
        :: "r"(a), "r"(parity) : "memory");
}

#define TC_LD_X32(r, tm) \
    asm volatile("tcgen05.ld.sync.aligned.32x32b.x32.b32 " \
        "{%0,%1,%2,%3,%4,%5,%6,%7,%8,%9,%10,%11,%12,%13,%14,%15," \
        "%16,%17,%18,%19,%20,%21,%22,%23,%24,%25,%26,%27,%28,%29,%30,%31}, [%32];" \
        : "=r"((r)[0]),"=r"((r)[1]),"=r"((r)[2]),"=r"((r)[3]), \
          "=r"((r)[4]),"=r"((r)[5]),"=r"((r)[6]),"=r"((r)[7]), \
          "=r"((r)[8]),"=r"((r)[9]),"=r"((r)[10]),"=r"((r)[11]), \
          "=r"((r)[12]),"=r"((r)[13]),"=r"((r)[14]),"=r"((r)[15]), \
          "=r"((r)[16]),"=r"((r)[17]),"=r"((r)[18]),"=r"((r)[19]), \
          "=r"((r)[20]),"=r"((r)[21]),"=r"((r)[22]),"=r"((r)[23]), \
          "=r"((r)[24]),"=r"((r)[25]),"=r"((r)[26]),"=r"((r)[27]), \
          "=r"((r)[28]),"=r"((r)[29]),"=r"((r)[30]),"=r"((r)[31]) \
        : "r"(tm))

#define TC_ST_X16(tm, r) \
    asm volatile("tcgen05.st.sync.aligned.32x32b.x16.b32 [%0], " \
        "{%1,%2,%3,%4,%5,%6,%7,%8,%9,%10,%11,%12,%13,%14,%15,%16};" \
        :: "r"(tm), \
           "r"((r)[0]),"r"((r)[1]),"r"((r)[2]),"r"((r)[3]), \
           "r"((r)[4]),"r"((r)[5]),"r"((r)[6]),"r"((r)[7]), \
           "r"((r)[8]),"r"((r)[9]),"r"((r)[10]),"r"((r)[11]), \
           "r"((r)[12]),"r"((r)[13]),"r"((r)[14]),"r"((r)[15]) \
        : "memory")

#define TC_ST_X32(tm, r) \
    asm volatile("tcgen05.st.sync.aligned.32x32b.x32.b32 [%0], " \
        "{%1,%2,%3,%4,%5,%6,%7,%8,%9,%10,%11,%12,%13,%14,%15,%16," \
        "%17,%18,%19,%20,%21,%22,%23,%24,%25,%26,%27,%28,%29,%30,%31,%32};" \
        :: "r"(tm), \
           "r"((r)[0]),"r"((r)[1]),"r"((r)[2]),"r"((r)[3]), \
           "r"((r)[4]),"r"((r)[5]),"r"((r)[6]),"r"((r)[7]), \
           "r"((r)[8]),"r"((r)[9]),"r"((r)[10]),"r"((r)[11]), \
           "r"((r)[12]),"r"((r)[13]),"r"((r)[14]),"r"((r)[15]), \
           "r"((r)[16]),"r"((r)[17]),"r"((r)[18]),"r"((r)[19]), \
           "r"((r)[20]),"r"((r)[21]),"r"((r)[22]),"r"((r)[23]), \
           "r"((r)[24]),"r"((r)[25]),"r"((r)[26]),"r"((r)[27]), \
           "r"((r)[28]),"r"((r)[29]),"r"((r)[30]),"r"((r)[31]) \
        : "memory")

// SMEM descriptor: SW128, version=1, SBO=64, LBO=1
__device__ __forceinline__ uint64_t mk_desc(uint32_t base) {
    const uint64_t B =
        (uint64_t(2) << 61) | (uint64_t(1) << 46) | (uint64_t(64) << 32) | (uint64_t(1) << 16);
    return B | ((uint64_t)(base >> 4) & 0x3FFF);
}

// TS-mode cg1 kind::f16 MMA (A in TMEM, bf16, fp32 acc)
__device__ __forceinline__ void mma_ts(uint32_t d, uint32_t a_tm, uint64_t b,
                                       uint32_t idesc, uint32_t acc) {
    asm volatile(
        "{\n\t.reg .pred p;\n\tsetp.ne.u32 p, %4, 0;\n\t"
        "tcgen05.mma.cta_group::1.kind::f16 [%0], [%1], %2, %3, {%5,%5,%5,%5}, p;\n\t}"
        :: "r"(d), "r"(a_tm), "l"(b), "r"(idesc), "r"(acc), "r"(0u) : "memory");
}
#endif  // TC_OK

// idesc: dtype=F32, atype=BF16, btype=BF16, N=128, M=128
#define IDESC_128 ((1u<<4)|(1u<<7)|(1u<<10)|((128u/8)<<17)|((128u/16)<<24))

// Blocked SW128 atom layout for a [128 rows, K cols] bf16 tile in smem.
__device__ __forceinline__ uint32_t lay128(int r, int c) {
    uint32_t off = ((uint32_t)(c >> 6) * 16u + (uint32_t)(r >> 3)) * 1024u
                 + (uint32_t)(r & 7) * 128u + (uint32_t)(c & 63) * 2u;
    return off ^ ((off >> 3) & 0x70u);
}
__device__ __forceinline__ uint32_t doff(int s) {
    return (uint32_t)(s >> 2) * 1024u + (uint32_t)(s & 3) * 2u;
}

// pack two fp32 -> bf16x2 (a = low element)
__device__ __forceinline__ uint32_t bf2(float a, float b) {
    uint32_t r;
    asm("cvt.rn.bf16x2.f32 %0, %1, %2;" : "=r"(r) : "f"(b), "f"(a));
    return r;
}
__device__ __forceinline__ void split2(float a, float b, uint32_t& hi, uint32_t& lo) {
    hi = bf2(a, b);
    float ra = __uint_as_float(hi << 16);
    float rb = __uint_as_float(hi & 0xFFFF0000u);
    lo = bf2(a - ra, b - rb);
}
// pack two fp32 -> fp16x2 (a = low element)
__device__ __forceinline__ uint32_t f2h2(float a, float b) {
    uint32_t r;
    asm("cvt.rn.f16x2.f32 %0, %1, %2;" : "=r"(r) : "f"(b), "f"(a));
    return r;
}

#if TC_OK
// W conv: fp32 [K,128] -> bf16 hi/lo [N=128,K] blocked SW128 in smem.
template<int K>
__device__ __forceinline__ void conv_w(char* smem, const float* Wb,
                                       int offH, int offL, int t) {
    #pragma unroll 2
    for (int i = t; i < (K / 2) * 32; i += 256) {
        int kp = i >> 5;
        int n4 = (i & 31) * 4;
        float4 v0 = *(const float4*)(Wb + (size_t)(2 * kp) * 128 + n4);
        float4 v1 = *(const float4*)(Wb + (size_t)(2 * kp + 1) * 128 + n4);
        const float* e0 = (const float*)&v0;
        const float* e1 = (const float*)&v1;
        #pragma unroll
        for (int j = 0; j < 4; j++) {
            uint32_t hi, lo;
            split2(e0[j], e1[j], hi, lo);
            uint32_t off = lay128(n4 + j, 2 * kp);
            *(uint32_t*)(smem + offH + off) = hi;
            *(uint32_t*)(smem + offL + off) = lo;
        }
    }
}

// issue 3-plane MMA chain: D = Ah*Wh + Ah*Wl + Al*Wh
template<int K>
__device__ __forceinline__ void mma_chain(uint32_t d, uint32_t tmemA,
                                          uint64_t wh, uint64_t wl) {
    constexpr int NS = K / 16;
    #pragma unroll
    for (int s = 0; s < NS; s++)
        mma_ts(d, tmemA + s * 8, wh + doff(s), IDESC_128, s > 0);
    #pragma unroll
    for (int s = 0; s < NS; s++)
        mma_ts(d, tmemA + s * 8, wl + doff(s), IDESC_128, 1);
    #pragma unroll
    for (int s = 0; s < NS; s++)
        mma_ts(d, tmemA + K / 2 + s * 8, wh + doff(s), IDESC_128, 1);
}
#endif

// ---------------------------------------------------------------------------
// Fused QKV: X fp16 in; Q/K/V fp16 out.  Grid = 576. 256 threads.
// ---------------------------------------------------------------------------
__global__ void __launch_bounds__(256) qkv_ts(
    const __half* __restrict__ X,
    const float* __restrict__ Wq, const float* __restrict__ Wk,
    const float* __restrict__ Wv,
    __half* __restrict__ Qo, __half* __restrict__ Ko, __half* __restrict__ Vo)
{
    extern __shared__ char smem[];
    const int t = threadIdx.x;
    const int bz = blockIdx.x;
    const __half* Ab = X + (size_t)bz * 512 * 128;

#if TC_OK
    constexpr int OFF_STG = 1024;              // 2 x 8KB fp16 stage
    constexpr int OFF_W   = OFF_STG + 32768;   // 6 x 32KB (q,k,v hi/lo)
    const uint32_t sb = smem_u32(smem);
    const int wid = t >> 5, lid = t & 31;

    if (t == 0) { MBAR_INIT(sb + 8, 1); MBAR_INIT(sb + 16, 1); }

    const float* Ws[3] = { Wq + (size_t)bz * 128 * 128,
                           Wk + (size_t)bz * 128 * 128,
                           Wv + (size_t)bz * 128 * 128 };
    #pragma unroll
    for (int w = 0; w < 3; w++)
        conv_w<128>(smem, Ws[w], OFF_W + w * 65536, OFF_W + w * 65536 + 32768, t);

    __syncthreads();
    if (wid == 0) { TC_ALLOC(sb, 512); TC_RELINQ(); }
    __syncthreads();
    uint32_t tmem;
    asm volatile("ld.shared.b32 %0, [%1];" : "=r"(tmem) : "r"(sb));
    const uint32_t D0 = tmem + 128, D1 = tmem + 256;

    uint64_t wdh[3], wdl[3];
    #pragma unroll
    for (int w = 0; w < 3; w++) {
        wdh[w] = mk_desc(sb + OFF_W + w * 65536);
        wdl[w] = mk_desc(sb + OFF_W + w * 65536 + 32768);
    }

    const int sub  = wid & 3;
    const int isLo = wid >> 2;
    const int row  = sub * 32 + lid;
    const int c0   = isLo * 64;

    // stage chunk g: 128 rows x 32 halves, 64B/row, swizzle slot (j+r)&3
    auto stage_issue = [&](int g) {
        const int tile = g >> 2;
        const int c    = g & 3;
        const __half* At = Ab + (size_t)tile * 128 * 128 + c * 32;
        const uint32_t dstb = sb + OFF_STG + (uint32_t)(g & 1) * 8192u;
        #pragma unroll
        for (int i = t; i < 512; i += 256) {
            int r = i >> 2, j = i & 3;
            const __half* src = At + (size_t)r * 128 + j * 8;
            uint32_t dst = dstb + (uint32_t)(r * 64 + (((j + r) & 3) << 4));
            asm volatile("cp.async.cg.shared.global [%0], [%1], 16;"
                         :: "r"(dst), "l"(src));
        }
        CP_COMMIT();
    };
    auto epiH = [&](uint32_t dbase, __half* outp, int tile) {
        __half* cp = outp + (size_t)bz * 512 * 128 + ((size_t)tile * 128 + row) * 128;
        #pragma unroll
        for (int cb = 0; cb < 2; cb++) {
            const int cc = c0 + cb * 32;
            uint32_t r[32];
            TC_LD_X32(r, dbase + cc);
            TC_WAIT_LD();
            #pragma unroll
            for (int q8 = 0; q8 < 8; q8++) {
                uint2 hv;
                hv.x = f2h2(__uint_as_float(r[q8*4+0]), __uint_as_float(r[q8*4+1]));
                hv.y = f2h2(__uint_as_float(r[q8*4+2]), __uint_as_float(r[q8*4+3]));
                *(uint2*)(cp + cc + q8 * 4) = hv;
            }
        }
        TC_FENCE_BEFORE();
    };

    stage_issue(0);
    int g = 0, p0 = 0, p1 = 0;

    for (int tile = 0; tile < 4; tile++) {
        #pragma unroll
        for (int c = 0; c < 4; c++, g++) {
            if (g + 1 < 16) { stage_issue(g + 1); CP_WAIT1(); }
            else            { CP_WAIT0(); }
            __syncthreads();
            const char* sbuf = smem + OFF_STG + (g & 1) * 8192;
            uint32_t rr[16];
            #pragma unroll
            for (int j = 0; j < 4; j++) {
                uint4 hv = *(const uint4*)(sbuf + row * 64 + (((j + row) & 3) << 4));
                const uint32_t* hw = (const uint32_t*)&hv;
                #pragma unroll
                for (int m = 0; m < 4; m++) {
                    float2 f = __half22float2(*(const __half2*)&hw[m]);
                    uint32_t hi, lo;
                    split2(f.x, f.y, hi, lo);
                    rr[j * 4 + m] = isLo ? lo : hi;
                }
            }
            TC_ST_X16(tmem + (uint32_t)isLo * 64 + c * 16, rr);
            __syncthreads();
        }
        TC_WAIT_ST();
        TC_FENCE_BEFORE();
        __syncthreads();

        if (wid == 0) {
            FENCE_ASYNC();
            TC_FENCE_AFTER();
            if (elect_one()) {
                mma_chain<128>(D0, tmem, wdh[0], wdl[0]); TC_COMMIT(sb + 8);
                mma_chain<128>(D1, tmem, wdh[1], wdl[1]); TC_COMMIT(sb + 16);
            }
        }

        mbar_wait(sb + 8, p0); p0 ^= 1;
        TC_FENCE_AFTER();
        epiH(D0, Qo, tile);
        __syncthreads();
        if (wid == 0) {
            TC_FENCE_AFTER();
            if (elect_one()) { mma_chain<128>(D0, tmem, wdh[2], wdl[2]); TC_COMMIT(sb + 8); }
        }
        mbar_wait(sb + 16, p1); p1 ^= 1;
        TC_FENCE_AFTER();
        epiH(D1, Ko, tile);
        mbar_wait(sb + 8, p0); p0 ^= 1;
        TC_FENCE_AFTER();
        epiH(D0, Vo, tile);
        __syncthreads();
    }

    __syncthreads();
    if (t == 0) { MBAR_INVAL(sb + 8); MBAR_INVAL(sb + 16); }
    __syncthreads();
    if (wid == 0) TC_DEALLOC(tmem, 512);
#else
    const float* Wsrc[3] = { Wq + (size_t)bz*128*128, Wk + (size_t)bz*128*128,
                             Wv + (size_t)bz*128*128 };
    __half* Outs[3] = { Qo + (size_t)bz*512*128, Ko + (size_t)bz*512*128,
                        Vo + (size_t)bz*512*128 };
    for (int w = 0; w < 3; w++)
        for (int i = t; i < 512 * 128; i += 256) {
            int r = i >> 7, c = i & 127;
            float s = 0.f;
            for (int k = 0; k < 128; k++)
                s += __half2float(Ab[(size_t)r * 128 + k]) * Wsrc[w][(size_t)k * 128 + c];
            Outs[w][i] = __float2half(s);
        }
#endif
}

// ---------------------------------------------------------------------------
// Fused 2-stage GEMM:
//   H = epi1(A@W1 [+b1][relu][+Res fp16]); Out = epi2(H@W2 [+b2][relu])
// AHALF: A fp16. OUTHALF: Out fp16. Res (when RES1) is fp16.
// TMEM: A[0,128) H[128,256) D0[256,384) D1[384,512).
// ---------------------------------------------------------------------------
template<int K1, bool BIAS1, bool RELU1, bool RES1, bool BIAS2, bool RELU2,
         bool AHALF, bool OUTHALF>
__global__ void __launch_bounds__(256) gemm2_ts(
    const void* __restrict__ Av,
    const float* __restrict__ W1, const float* __restrict__ b1,
    const void* __restrict__ Resv,
    const float* __restrict__ W2, const float* __restrict__ b2,
    void* __restrict__ Outv)
{
    extern __shared__ char smem[];
    const int t = threadIdx.x;
    const int bz = blockIdx.x;
    const __half* Rb = RES1 ? (const __half*)Resv + (size_t)bz * 512 * 128 : nullptr;

#if TC_OK
    constexpr int W1BYTES = (K1 >= 128) ? 32768 : 16384;
    constexpr int OFF_STG = 2048;
    constexpr int OFF_W1H = OFF_STG + 32768;
    constexpr int OFF_W1L = OFF_W1H + W1BYTES;
    constexpr int OFF_W2H = OFF_W1L + W1BYTES;
    constexpr int OFF_W2L = OFF_W2H + 32768;
    constexpr int NCHK1 = K1 / 32;
    constexpr int NG = 4 * NCHK1;

    const uint32_t sb = smem_u32(smem);
    const int wid = t >> 5, lid = t & 31;
    float* bias1_s = (float*)(smem + 64);
    float* bias2_s = (float*)(smem + 576);

    if (t == 0) { MBAR_INIT(sb + 8, 1); MBAR_INIT(sb + 16, 1); }

    conv_w<K1 >(smem, W1 + (size_t)bz * K1 * 128, OFF_W1H, OFF_W1L, t);
    conv_w<128>(smem, W2 + (size_t)bz * 128 * 128, OFF_W2H, OFF_W2L, t);
    if (BIAS1 && t < 128) bias1_s[t] = b1[(size_t)bz * 128 + t];
    if (BIAS2 && t < 128) bias2_s[t] = b2[(size_t)bz * 128 + t];

    __syncthreads();
    if (wid == 0) { TC_ALLOC(sb, 512); TC_RELINQ(); }
    __syncthreads();
    uint32_t tmem;
    asm volatile("ld.shared.b32 %0, [%1];" : "=r"(tmem) : "r"(sb));
    const uint32_t TM_A = tmem;
    const uint32_t TM_H = tmem + 128;
    const uint32_t D0   = tmem + 256;
    const uint32_t D1   = tmem + 384;

    const uint64_t w1h = mk_desc(sb + OFF_W1H), w1l = mk_desc(sb + OFF_W1L);
    const uint64_t w2h = mk_desc(sb + OFF_W2H), w2l = mk_desc(sb + OFF_W2L);

    const int sub  = wid & 3;
    const int isLo = wid >> 2;
    const int row  = sub * 32 + lid;
    const int ch   = isLo;
    const int c0   = ch * 64;

    int g = 0;

    auto stage_issue = [&](int gg) {
        const int tile = gg / NCHK1;
        const int c    = gg - tile * NCHK1;
        if (AHALF) {
            const __half* At = (const __half*)Av
                + (size_t)bz * 512 * K1 + (size_t)tile * 128 * K1 + c * 32;
            const uint32_t dstb = sb + OFF_STG + (uint32_t)(gg & 1) * 8192u;
            #pragma unroll
            for (int i = t; i < 512; i += 256) {
                int r = i >> 2, j = i & 3;
                const __half* src = At + (size_t)r * K1 + j * 8;
                uint32_t dst = dstb + (uint32_t)(r * 64 + (((j + r) & 3) << 4));
                asm volatile("cp.async.cg.shared.global [%0], [%1], 16;"
                             :: "r"(dst), "l"(src));
            }
        } else {
            const float* At = (const float*)Av
                + (size_t)bz * 512 * K1 + (size_t)tile * 128 * K1 + c * 32;
            const uint32_t dstb = sb + OFF_STG + (uint32_t)(gg & 1) * 16384u;
            #pragma unroll
            for (int i = t; i < 1024; i += 256) {
                int r = i >> 3, j = i & 7;
                const float* src = At + (size_t)r * K1 + j * 4;
                uint32_t dst = dstb + (uint32_t)(r * 32 + (((j + r) & 7) << 2)) * 4u;
                asm volatile("cp.async.cg.shared.global [%0], [%1], 16;"
                             :: "r"(dst), "l"(src));
            }
        }
        CP_COMMIT();
    };

    auto convA = [&]() {
        #pragma unroll
        for (int c = 0; c < NCHK1; c++, g++) {
            if (g + 1 < NG) { stage_issue(g + 1); CP_WAIT1(); }
            else            { CP_WAIT0(); }
            __syncthreads();
            uint32_t rr[16];
            if (AHALF) {
                const char* sbuf = smem + OFF_STG + (g & 1) * 8192;
                #pragma unroll
                for (int j = 0; j < 4; j++) {
                    uint4 hv = *(const uint4*)(sbuf + row * 64 + (((j + row) & 3) << 4));
                    const uint32_t* hw = (const uint32_t*)&hv;
                    #pragma unroll
                    for (int m = 0; m < 4; m++) {
                        float2 f = __half22float2(*(const __half2*)&hw[m]);
                        uint32_t hi, lo;
                        split2(f.x, f.y, hi, lo);
                        rr[j * 4 + m] = isLo ? lo : hi;
                    }
                }
            } else {
                const float* sbuf = (const float*)(smem + OFF_STG + (g & 1) * 16384);
                #pragma unroll
                for (int j = 0; j < 8; j++) {
                    float4 v = *(const float4*)(sbuf + row * 32 + (((j + row) & 7) << 2));
                    uint32_t h0 = bf2(v.x, v.y);
                    uint32_t h1 = bf2(v.z, v.w);
                    if (!isLo) { rr[2*j] = h0; rr[2*j+1] = h1; }
                    else {
                        float ax = __uint_as_float(h0 << 16);
                        float ay = __uint_as_float(h0 & 0xFFFF0000u);
                        float az = __uint_as_float(h1 << 16);
                        float aw = __uint_as_float(h1 & 0xFFFF0000u);
                        rr[2*j]   = bf2(v.x - ax, v.y - ay);
                        rr[2*j+1] = bf2(v.z - az, v.w - aw);
                    }
                }
            }
            TC_ST_X16(TM_A + (uint32_t)isLo * (K1 / 2) + c * 16, rr);
            __syncthreads();
        }
        TC_WAIT_ST();
        TC_FENCE_BEFORE();
        __syncthreads();
    };

    // prologue: conv A(0), issue MMA1(0)
    stage_issue(0);
    convA();
    if (wid == 0) {
        FENCE_ASYNC();
        TC_FENCE_AFTER();
        if (elect_one()) { mma_chain<K1>(D0, TM_A, w1h, w1l); TC_COMMIT(sb + 8); }
    }

    int p0 = 0, p1 = 0;

    for (int tile = 0; tile < 4; tile++) {
        // ---- wait MMA1(tile); epi1: D0 (+res/b1/relu) -> bf16 hi/lo -> TM_H ----
        mbar_wait(sb + 8, p0); p0 ^= 1;
        TC_FENCE_AFTER();
        {
            float d[64];
            #pragma unroll
            for (int cb = 0; cb < 2; cb++) {
                uint32_t r[32];
                TC_LD_X32(r, D0 + c0 + cb * 32);
                TC_WAIT_LD();
                #pragma unroll
                for (int q = 0; q < 32; q++) d[cb * 32 + q] = __uint_as_float(r[q]);
            }
            if (RES1) {
                const __half* rp = Rb + ((size_t)tile * 128 + row) * 128 + c0;
                #pragma unroll
                for (int q8 = 0; q8 < 8; q8++) {
                    uint4 hv = *(const uint4*)(rp + q8 * 8);
                    const uint32_t* hw = (const uint32_t*)&hv;
                    #pragma unroll
                    for (int m = 0; m < 4; m++) {
                        float2 f = __half22float2(*(const __half2*)&hw[m]);
                        d[q8*8 + m*2 + 0] += f.x;
                        d[q8*8 + m*2 + 1] += f.y;
                    }
                }
            }
            if (BIAS1) {
                #pragma unroll
                for (int q = 0; q < 64; q++) d[q] += bias1_s[c0 + q];
            }
            if (RELU1) {
                #pragma unroll
                for (int q = 0; q < 64; q++) d[q] = fmaxf(d[q], 0.f);
            }
            uint32_t hi[32], lo[32];
            #pragma unroll
            for (int j = 0; j < 32; j++) split2(d[2*j], d[2*j+1], hi[j], lo[j]);
            TC_ST_X32(TM_H + ch * 32, hi);
            TC_ST_X32(TM_H + 64 + ch * 32, lo);
            TC_WAIT_ST();
            TC_FENCE_BEFORE();
        }
        __syncthreads();

        // ---- issue MMA2(tile) -> D1 ----
        if (wid == 0) {
            TC_FENCE_AFTER();
            if (elect_one()) { mma_chain<128>(D1, TM_H, w2h, w2l); TC_COMMIT(sb + 16); }
        }

        // ---- overlap: conv A(tile+1) + issue MMA1(tile+1) while MMA2 runs ----
        if (tile + 1 < 4) {
            convA();
            if (wid == 0) {
                FENCE_ASYNC();
                TC_FENCE_AFTER();
                if (elect_one()) { mma_chain<K1>(D0, TM_A, w1h, w1l); TC_COMMIT(sb + 8); }
            }
        }

        // ---- wait MMA2(tile); epi2 -> Out ----
        mbar_wait(sb + 16, p1); p1 ^= 1;
        TC_FENCE_AFTER();
        {
            #pragma unroll
            for (int cb = 0; cb < 2; cb++) {
                const int cc = c0 + cb * 32;
                uint32_t r[32];
                TC_LD_X32(r, D1 + cc);
                TC_WAIT_LD();
                #pragma unroll
                for (int q8 = 0; q8 < 8; q8++) {
                    float4 v = make_float4(
                        __uint_as_float(r[q8*4+0]), __uint_as_float(r[q8*4+1]),
                        __uint_as_float(r[q8*4+2]), __uint_as_float(r[q8*4+3]));
                    if (BIAS2) {
                        v.x += bias2_s[cc + q8*4+0]; v.y += bias2_s[cc + q8*4+1];
                        v.z += bias2_s[cc + q8*4+2]; v.w += bias2_s[cc + q8*4+3];
                    }
                    if (RELU2) {
                        v.x = fmaxf(v.x, 0.f); v.y = fmaxf(v.y, 0.f);
                        v.z = fmaxf(v.z, 0.f); v.w = fmaxf(v.w, 0.f);
                    }
                    if (OUTHALF) {
                        __half* cp = (__half*)Outv + (size_t)bz * 512 * 128
                                   + ((size_t)tile * 128 + row) * 128;
                        uint2 hv;
                        hv.x = f2h2(v.x, v.y);
                        hv.y = f2h2(v.z, v.w);
                        *(uint2*)(cp + cc + q8 * 4) = hv;
                    } else {
                        float* cp = (float*)Outv + (size_t)bz * 512 * 128
                                  + ((size_t)tile * 128 + row) * 128;
                        *(float4*)(cp + cc + q8 * 4) = v;
                    }
                }
            }
            TC_FENCE_BEFORE();
        }
    }

    __syncthreads();
    if (t == 0) { MBAR_INVAL(sb + 8); MBAR_INVAL(sb + 16); }
    __syncthreads();
    if (wid == 0) TC_DEALLOC(tmem, 512);
#else
    float* Hs = (float*)(smem + 2048);   // 128 x 132
    const float* W1b = W1 + (size_t)bz * K1 * 128;
    const float* W2b = W2 + (size_t)bz * 128 * 128;
    for (int tile = 0; tile < 4; tile++) {
        for (int i = t; i < 128 * 128; i += 256) {
            int r = i >> 7, c = i & 127;
            float s = 0.f;
            for (int k = 0; k < K1; k++) {
                float av = AHALF
                    ? __half2float(((const __half*)Av)[(size_t)bz*512*K1
                        + ((size_t)tile*128 + r) * K1 + k])
                    : ((const float*)Av)[(size_t)bz*512*K1
                        + ((size_t)tile*128 + r) * K1 + k];
                s += av * W1b[(size_t)k * 128 + c];
            }
            if (BIAS1) s += b1[(size_t)bz * 128 + c];
            if (RES1)  s += __half2float(Rb[((size_t)tile * 128 + r) * 128 + c]);
            if (RELU1) s = fmaxf(s, 0.f);
            Hs[r * 132 + c] = s;
        }
        __syncthreads();
        for (int i = t; i < 128 * 128; i += 256) {
            int r = i >> 7, c = i & 127;
            float s = 0.f;
            for (int k = 0; k < 128; k++)
                s += Hs[r * 132 + k] * W2b[(size_t)k * 128 + c];
            if (BIAS2) s += b2[(size_t)bz * 128 + c];
            if (RELU2) s = fmaxf(s, 0.f);
            size_t oidx = (size_t)bz*512*128 + ((size_t)tile * 128 + r) * 128 + c;
            if (OUTHALF) ((__half*)Outv)[oidx] = __float2half(s);
            else         ((float*)Outv)[oidx] = s;
        }
        __syncthreads();
    }
#endif
}

// ---------------------------------------------------------------------------
// Single GEMM (predictor): C = relu(A@W + b). Grid = 64. A,C fp32.
// ---------------------------------------------------------------------------
template<int K, bool RELU, bool BIAS>
__global__ void __launch_bounds__(256) gemm_ts(
    const float* __restrict__ A,
    const float* __restrict__ W,
    const float* __restrict__ bias,
    float* __restrict__ C)
{
    extern __shared__ char smem[];
    const int t = threadIdx.x;
    const int bz = blockIdx.x;
    const float* Ab = A + (size_t)bz * 512 * K;
    const float* Wb = W + (size_t)bz * K * 128;
    float*       Cb = C + (size_t)bz * 512 * 128;

#if TC_OK
    constexpr int WBYTES  = 1024 * 16 * ((K >= 128) ? 2 : 1);
    constexpr int OFF_STG = 1024;
    constexpr int OFF_WH  = OFF_STG + 32768;
    constexpr int OFF_WL  = OFF_WH + WBYTES;
    constexpr int NCHK = K / 32;
    constexpr int NG   = 4 * NCHK;

    const uint32_t sb = smem_u32(smem);
    const int wid = t >> 5, lid = t & 31;
    float* bias_s = (float*)(smem + 32);
    float* stg    = (float*)(smem + OFF_STG);

    if (t == 0) MBAR_INIT(sb + 8, 1);
    conv_w<K>(smem, Wb, OFF_WH, OFF_WL, t);
    if (BIAS && t < 128) bias_s[t] = bias[(size_t)bz * 128 + t];
    __syncthreads();
    if (wid == 0) { TC_ALLOC(sb, 256); TC_RELINQ(); }
    __syncthreads();
    uint32_t tmem;
    asm volatile("ld.shared.b32 %0, [%1];" : "=r"(tmem) : "r"(sb));

    const uint64_t whd = mk_desc(sb + OFF_WH);
    const uint64_t wld = mk_desc(sb + OFF_WL);
    const int sub  = wid & 3;
    const int isLo = wid >> 2;
    const int row  = sub * 32 + lid;

    auto stage_issue = [&](int g) {
        const int tile = g / NCHK;
        const int c    = g - tile * NCHK;
        const float* At = Ab + (size_t)tile * 128 * K + c * 32;
        const uint32_t dstb = sb + OFF_STG + (uint32_t)(g & 1) * 16384u;
        #pragma unroll
        for (int i = t; i < 1024; i += 256) {
            int r = i >> 3, j = i & 7;
            const float* src = At + (size_t)r * K + j * 4;
            uint32_t dst = dstb + (uint32_t)(r * 32 + (((j + r) & 7) << 2)) * 4u;
            asm volatile("cp.async.cg.shared.global [%0], [%1], 16;"
                         :: "r"(dst), "l"(src));
        }
        CP_COMMIT();
    };

    stage_issue(0);
    int g = 0, parity = 0;
    for (int tile = 0; tile < 4; tile++) {
        #pragma unroll
        for (int c = 0; c < NCHK; c++, g++) {
            if (g + 1 < NG) { stage_issue(g + 1); CP_WAIT1(); }
            else            { CP_WAIT0(); }
            __syncthreads();
            const float* sbuf = stg + (g & 1) * 4096;
            uint32_t rr[16];
            #pragma unroll
            for (int j = 0; j < 8; j++) {
                float4 v = *(const float4*)(sbuf + row * 32 + (((j + row) & 7) << 2));
                uint32_t h0 = bf2(v.x, v.y);
                uint32_t h1 = bf2(v.z, v.w);
                if (!isLo) { rr[2*j] = h0; rr[2*j+1] = h1; }
                else {
                    float ax = __uint_as_float(h0 << 16);
                    float ay = __uint_as_float(h0 & 0xFFFF0000u);
                    float az = __uint_as_float(h1 << 16);
                    float aw = __uint_as_float(h1 & 0xFFFF0000u);
                    rr[2*j]   = bf2(v.x - ax, v.y - ay);
                    rr[2*j+1] = bf2(v.z - az, v.w - aw);
                }
            }
            TC_ST_X16(tmem + (uint32_t)isLo * (K / 2) + c * 16, rr);
            __syncthreads();
        }
        TC_WAIT_ST();
        TC_FENCE_BEFORE();
        __syncthreads();
        if (wid == 0) {
            FENCE_ASYNC();
            TC_FENCE_AFTER();
            if (elect_one()) { mma_chain<K>(tmem + 128, tmem, whd, wld); TC_COMMIT(sb + 8); }
        }
        mbar_wait(sb + 8, parity); parity ^= 1;
        TC_FENCE_AFTER();
        {
            float* cp = Cb + ((size_t)tile * 128 + row) * 128;
            const int c0 = isLo * 64;
            #pragma unroll
            for (int cb = 0; cb < 2; cb++) {
                const int cc = c0 + cb * 32;
                uint32_t r[32];
                TC_LD_X32(r, tmem + 128 + cc);
                TC_WAIT_LD();
                #pragma unroll
                for (int q8 = 0; q8 < 8; q8++) {
                    float4 v = make_float4(
                        __uint_as_float(r[q8*4+0]), __uint_as_float(r[q8*4+1]),
                        __uint_as_float(r[q8*4+2]), __uint_as_float(r[q8*4+3]));
                    if (BIAS) {
                        v.x += bias_s[cc+q8*4+0]; v.y += bias_s[cc+q8*4+1];
                        v.z += bias_s[cc+q8*4+2]; v.w += bias_s[cc+q8*4+3];
                    }
                    if (RELU) {
                        v.x = fmaxf(v.x, 0.f); v.y = fmaxf(v.y, 0.f);
                        v.z = fmaxf(v.z, 0.f); v.w = fmaxf(v.w, 0.f);
                    }
                    *(float4*)(cp + cc + q8 * 4) = v;
                }
            }
            TC_FENCE_BEFORE();
        }
    }
    __syncthreads();
    if (t == 0) MBAR_INVAL(sb + 8);
    __syncthreads();
    if (wid == 0) TC_DEALLOC(tmem, 256);
#else
    for (int i = t; i < 512 * 128; i += 256) {
        int r = i >> 7, c = i & 127;
        float s = 0.f;
        for (int k = 0; k < K; k++)
            s += Ab[(size_t)r * K + k] * Wb[(size_t)k * 128 + c];
        if (BIAS) s += bias[(size_t)bz * 128 + c];
        if (RELU) s = fmaxf(s, 0.f);
        Cb[(size_t)r * 128 + c] = s;
    }
#endif
}

// ---------------------------------------------------------------------------
// Attention core: Q,K,V fp16 in (16B loads); T fp16 out. 256 threads, 2 batches.
// ---------------------------------------------------------------------------
__global__ void __launch_bounds__(256) attn_kernel(
    const __half* __restrict__ Q, const __half* __restrict__ Kk,
    const __half* __restrict__ V, __half* __restrict__ T)
{
    const int blk = blockIdx.x;
    const int ef  = blk >> 8;
    const int bp  = (blk & 255) << 1;

    __shared__ float qs[2][NO][132];
    __shared__ float ks[2][NO][132];
    __shared__ float vs[2][NO][132];
    __shared__ float lg[2][4][NO][12];

    const int t  = threadIdx.x;
    const int g  = t >> 7;
    const int tl = t & 127;
    const int b  = bp + g;

    for (int idx = tl; idx < NO * 16; idx += 128) {
        int o  = idx >> 4;
        int c8 = (idx & 15) * 8;
        size_t ga = ((size_t)(ef * NO + o) * NB + b) * 128 + c8;
        uint4 qv = *(const uint4*)(Q + ga);
        uint4 kv = *(const uint4*)(Kk + ga);
        uint4 vv = *(const uint4*)(V + ga);
        const uint32_t* qw = (const uint32_t*)&qv;
        const uint32_t* kw = (const uint32_t*)&kv;
        const uint32_t* vw = (const uint32_t*)&vv;
        #pragma unroll
        for (int m = 0; m < 4; m++) {
            float2 fq = __half22float2(*(const __half2*)&qw[m]);
            float2 fk = __half22float2(*(const __half2*)&kw[m]);
            float2 fv = __half22float2(*(const __half2*)&vw[m]);
            qs[g][o][c8 + 2*m + 0] = fq.x; qs[g][o][c8 + 2*m + 1] = fq.y;
            ks[g][o][c8 + 2*m + 0] = fk.x; ks[g][o][c8 + 2*m + 1] = fk.y;
            vs[g][o][c8 + 2*m + 0] = fv.x; vs[g][o][c8 + 2*m + 1] = fv.y;
        }
    }
    __syncthreads();

    const float scale = 0.17677669529663687f;
    for (int e = tl; e < 4 * NO * NO; e += 128) {
        int h   = e / (NO * NO);
        int rem = e - h * NO * NO;
        int i   = rem / NO;
        int j   = rem - i * NO;
        float s = 0.f;
        #pragma unroll
        for (int d = 0; d < 32; d++) s += qs[g][i][h * 32 + d] * ks[g][j][h * 32 + d];
        lg[g][h][i][j] = s * scale;
    }
    __syncthreads();

    if (tl < 4 * NO) {
        int h = tl / NO, i = tl - (tl / NO) * NO;
        float mx = -1e30f;
        #pragma unroll
        for (int j = 0; j < NO; j++) mx = fmaxf(mx, lg[g][h][i][j]);
        float ex[NO]; float s = 0.f;
        #pragma unroll
        for (int j = 0; j < NO; j++) { ex[j] = __expf(lg[g][h][i][j] - mx); s += ex[j]; }
        float inv = 1.f / s;
        #pragma unroll
        for (int j = 0; j < NO; j++) lg[g][h][i][j] = ex[j] * inv;
    }
    __syncthreads();

    const int c = tl, h = c >> 5;
    #pragma unroll
    for (int i = 0; i < NO; i++) {
        float s = 0.f;
        #pragma unroll
        for (int j = 0; j < NO; j++) s += lg[g][h][i][j] * vs[g][j][c];
        T[((size_t)(ef * NO + i) * NB + b) * 128 + c] = __float2half(s);
    }
}

__global__ void __launch_bounds__(256) pool_kernel(
    const __half* __restrict__ Hin, float* __restrict__ P)
{
    int idx = blockIdx.x * 256 + threadIdx.x;
    if (idx >= NEF * NB * NDH) return;
    int c = idx & 127, b = (idx >> 7) & 511, ef = idx >> 16;
    float s = 0.f;
    #pragma unroll
    for (int o = 0; o < NO; o++)
        s += __half2float(Hin[((size_t)(ef * NO + o) * NB + b) * 128 + c]);
    P[idx] = s * (1.f / 9.f);
}

__global__ void __launch_bounds__(256) final_kernel(
    const float* __restrict__ A, const float* __restrict__ W,
    const float* __restrict__ bias, float* __restrict__ Out)
{
    const int mt = blockIdx.x;
    const int ef = blockIdx.y;
    __shared__ float As[32][128];
    __shared__ float Ws[128][NFINAL];
    __shared__ float bs[NFINAL];
    const int t = threadIdx.x;
    const float* Ab = A + ((size_t)ef * NB + mt * 32) * 128;
    for (int i = t; i < 32 * 128 / 4; i += 256)
        ((float4*)&As[0][0])[i] = ((const float4*)Ab)[i];
    for (int i = t; i < 128 * NFINAL; i += 256)
        Ws[i / NFINAL][i % NFINAL] = W[(size_t)ef * 128 * NFINAL + i];
    if (t < NFINAL) bs[t] = bias[ef * NFINAL + t];
    __syncthreads();
    for (int idx = t; idx < 32 * NFINAL; idx += 256) {
        int r = idx / NFINAL, j = idx - r * NFINAL;
        float s = bs[j];
        #pragma unroll 16
        for (int k = 0; k < 128; k++) s += As[r][k] * Ws[k][j];
        Out[((size_t)ef * NB + mt * 32 + r) * NFINAL + j] = s;
    }
}

// ---------------------------------------------------------------------------
extern "C" void kernel_launch(void* const* d_in, const int* in_sizes, int n_in,
                              void* d_out, int out_size)
{
    const float* x   = (const float*)d_in[0];
    const float* fw1 = (const float*)d_in[1];
    const float* fb1 = (const float*)d_in[2];
    const float* fw2 = (const float*)d_in[3];
    const float* fb2 = (const float*)d_in[4];
    const float* aw[2][5];
    const float* apb[2];
    for (int i = 0; i < 2; i++) {
        for (int n = 0; n < 5; n++) aw[i][n] = (const float*)d_in[5 + i * 6 + n];
        apb[i] = (const float*)d_in[5 + i * 6 + 5];
    }
    const float* pw1 = (const float*)d_in[17];
    const float* pb1 = (const float*)d_in[18];
    const float* pw2 = (const float*)d_in[19];
    const float* pb2 = (const float*)d_in[20];
    float* out = (float*)d_out;

    __half *H1, *H2, *Q, *K, *V, *T;
    float *PO, *P;
    cudaGetSymbolAddress((void**)&H1, g_h1);
    cudaGetSymbolAddress((void**)&H2, g_h2);
    cudaGetSymbolAddress((void**)&Q,  g_q);
    cudaGetSymbolAddress((void**)&K,  g_k);
    cudaGetSymbolAddress((void**)&V,  g_v);
    cudaGetSymbolAddress((void**)&T,  g_t);
    cudaGetSymbolAddress((void**)&PO, g_po);
    cudaGetSymbolAddress((void**)&P,  g_p);

    const int SMQKV = 1024 + 32768 + 6 * 32768;             // 230,400
    const int SMF12 = 2048 + 32768 + 2 * 16384 + 2 * 32768; // 133,120
    const int SMWP  = 2048 + 32768 + 4 * 32768;             // 165,888
    const int SMPRD = 1024 + 32768 + 2 * 32768;             // 99,328

    cudaFuncSetAttribute(qkv_ts, cudaFuncAttributeMaxDynamicSharedMemorySize, SMQKV);
    cudaFuncSetAttribute(
        gemm2_ts<32, true, true, false, true, true, false, true>,
        cudaFuncAttributeMaxDynamicSharedMemorySize, SMF12);
    cudaFuncSetAttribute(
        gemm2_ts<128, false, false, true, true, true, true, true>,
        cudaFuncAttributeMaxDynamicSharedMemorySize, SMWP);
    cudaFuncSetAttribute(gemm_ts<128, true, true>,
        cudaFuncAttributeMaxDynamicSharedMemorySize, SMPRD);

    // fused feature_fc (fc1 + fc2): x fp32 -> H2 fp16
    gemm2_ts<32, true, true, false, true, true, false, true><<<NCH, 256, SMF12>>>(
        x, fw1, fb1, nullptr, fw2, fb2, H2);

    // two ChannelMHA blocks (all intermediates fp16)
    const __half* X = H2;
    __half* Y = H1;
    for (int a = 0; a < 2; a++) {
        qkv_ts<<<NCH, 256, SMQKV>>>(X, aw[a][0], aw[a][1], aw[a][2], Q, K, V);
        attn_kernel<<<NEF * NB / 2, 256>>>(Q, K, V, T);
        // fused: Y = relu((T@wo + X) @ pw + pb)
        gemm2_ts<128, false, false, true, true, true, true, true><<<NCH, 256, SMWP>>>(
            T, aw[a][3], nullptr, X, aw[a][4], apb[a], Y);
        const __half* nX = Y;
        Y = (a == 0) ? H2 : H1;
        X = nX;
    }
    // X == H2 after the loop

    pool_kernel<<<(NEF * NB * NDH + 255) / 256, 256>>>(X, PO);
    gemm_ts<128, true, true><<<NEF, 256, SMPRD>>>(PO, pw1, pb1, P);
    final_kernel<<<dim3(16, NEF), 256>>>(P, pw2, pb2, out);
}

// round 17
// speedup vs baseline: 1.2773x; 1.1977x over previous
#include <cuda_runtime.h>
#include <cuda_fp16.h>
#include <cstdint>

// ---------------------------------------------------------------------------
// EnsembleCausalPredictor: E=4, F=16, O=9, B=512, DIN=32, DH=128, H=4, DK=32
// Single-plane FP16 tcgen05 MMAs (fp32 accumulate); all intermediates fp16.
// All GEMM CTAs sized for 2 CTAs/SM (smem <= 113KB, TMEM 256, lb(256,2)).
// ---------------------------------------------------------------------------

#define NE 4
#define NF 16
#define NO 9
#define NB 512
#define NDH 128
#define NFINAL 17
#define NEF (NE*NF)        // 64
#define NCH (NEF*NO)       // 576

#define HBUF (NCH*NB*NDH)
__device__ __half g_h1[HBUF];
__device__ __half g_h2[HBUF];
__device__ __half g_q [HBUF];
__device__ __half g_k [HBUF];
__device__ __half g_v [HBUF];
__device__ __half g_t [HBUF];
__device__ float g_po[NEF*NB*NDH];
__device__ float g_p [NEF*NB*NDH];

#if defined(__CUDA_ARCH_FEAT_SM103_ALL) || defined(__CUDA_ARCH_FEAT_SM100_ALL)
#define TC_OK 1
#else
#define TC_OK 0
#endif

// ------------------------------- PTX helpers ------------------------------
__device__ __forceinline__ uint32_t smem_u32(const void* p) {
    uint32_t a;
    asm("{ .reg .u64 tmp; cvta.to.shared.u64 tmp, %1; cvt.u32.u64 %0, tmp; }"
        : "=r"(a) : "l"(p));
    return a;
}

#if TC_OK
__device__ __forceinline__ uint32_t elect_one() {
    uint32_t p;
    asm volatile("{\n\t.reg .pred p;\n\telect.sync _|p, 0xFFFFFFFF;\n\t"
                 "selp.b32 %0, 1, 0, p;\n\t}" : "=r"(p));
    return p;
}
#define TC_ALLOC(sa, n) \
    asm volatile("tcgen05.alloc.cta_group::1.sync.aligned.shared::cta.b32 [%0], %1;" \
                 :: "r"(sa), "r"(n) : "memory")
#define TC_RELINQ() \
    asm volatile("tcgen05.relinquish_alloc_permit.cta_group::1.sync.aligned;")
#define TC_DEALLOC(tm, n) \
    asm volatile("tcgen05.dealloc.cta_group::1.sync.aligned.b32 %0, %1;" :: "r"(tm), "r"(n))
#define MBAR_INIT(a, c) \
    asm volatile("mbarrier.init.shared.b64 [%0], %1;" :: "r"(a), "r"(c) : "memory")
#define MBAR_INVAL(a) \
    asm volatile("mbarrier.inval.shared.b64 [%0];" :: "r"(a) : "memory")
#define TC_COMMIT(a) \
    asm volatile("tcgen05.commit.cta_group::1.mbarrier::arrive::one.shared::cluster.b64 [%0];" \
                 :: "r"(a) : "memory")
#define TC_WAIT_LD()  asm volatile("tcgen05.wait::ld.sync.aligned;" ::: "memory")
#define TC_WAIT_ST()  asm volatile("tcgen05.wait::st.sync.aligned;" ::: "memory")
#define TC_FENCE_AFTER()  asm volatile("tcgen05.fence::after_thread_sync;" ::: "memory")
#define TC_FENCE_BEFORE() asm volatile("tcgen05.fence::before_thread_sync;" ::: "memory")
#define FENCE_ASYNC() asm volatile("fence.proxy.async.shared::cta;" ::: "memory")
#define CP_COMMIT() asm volatile("cp.async.commit_group;" ::: "memory")
#define CP_WAIT1()  asm volatile("cp.async.wait_group 1;" ::: "memory")
#define CP_WAIT0()  asm volatile("cp.async.wait_group 0;" ::: "memory")

__device__ __forceinline__ void mbar_wait(uint32_t a, uint32_t parity) {
    asm volatile(
        "{\n\t.reg .pred P1;\n\t"
        "WAIT_LOOP_%=:\n\t"
        "mbarrier.try_wait.parity.acquire.cta.shared::cta.b64 P1, [%0], %1, 0x989680;\n\t"
        "@P1 bra.uni WAIT_DONE_%=;\n\t"
        "bra.uni WAIT_LOOP_%=;\n\t"
        "WAIT_DONE_%=:\n\t}"
        :: "r"(a), "r"(parity) : "memory");
}

#define TC_LD_X32(r, tm) \
    asm volatile("tcgen05.ld.sync.aligned.32x32b.x32.b32 " \
        "{%0,%1,%2,%3,%4,%5,%6,%7,%8,%9,%10,%11,%12,%13,%14,%15," \
        "%16,%17,%18,%19,%20,%21,%22,%23,%24,%25,%26,%27,%28,%29,%30,%31}, [%32];" \
        : "=r"((r)[0]),"=r"((r)[1]),"=r"((r)[2]),"=r"((r)[3]), \
          "=r"((r)[4]),"=r"((r)[5]),"=r"((r)[6]),"=r"((r)[7]), \
          "=r"((r)[8]),"=r"((r)[9]),"=r"((r)[10]),"=r"((r)[11]), \
          "=r"((r)[12]),"=r"((r)[13]),"=r"((r)[14]),"=r"((r)[15]), \
          "=r"((r)[16]),"=r"((r)[17]),"=r"((r)[18]),"=r"((r)[19]), \
          "=r"((r)[20]),"=r"((r)[21]),"=r"((r)[22]),"=r"((r)[23]), \
          "=r"((r)[24]),"=r"((r)[25]),"=r"((r)[26]),"=r"((r)[27]), \
          "=r"((r)[28]),"=r"((r)[29]),"=r"((r)[30]),"=r"((r)[31]) \
        : "r"(tm))

#define TC_ST_X8(tm, r) \
    asm volatile("tcgen05.st.sync.aligned.32x32b.x8.b32 [%0], " \
        "{%1,%2,%3,%4,%5,%6,%7,%8};" \
        :: "r"(tm), \
           "r"((r)[0]),"r"((r)[1]),"r"((r)[2]),"r"((r)[3]), \
           "r"((r)[4]),"r"((r)[5]),"r"((r)[6]),"r"((r)[7]) \
        : "memory")

#define TC_ST_X32(tm, r) \
    asm volatile("tcgen05.st.sync.aligned.32x32b.x32.b32 [%0], " \
        "{%1,%2,%3,%4,%5,%6,%7,%8,%9,%10,%11,%12,%13,%14,%15,%16," \
        "%17,%18,%19,%20,%21,%22,%23,%24,%25,%26,%27,%28,%29,%30,%31,%32};" \
        :: "r"(tm), \
           "r"((r)[0]),"r"((r)[1]),"r"((r)[2]),"r"((r)[3]), \
           "r"((r)[4]),"r"((r)[5]),"r"((r)[6]),"r"((r)[7]), \
           "r"((r)[8]),"r"((r)[9]),"r"((r)[10]),"r"((r)[11]), \
           "r"((r)[12]),"r"((r)[13]),"r"((r)[14]),"r"((r)[15]), \
           "r"((r)[16]),"r"((r)[17]),"r"((r)[18]),"r"((r)[19]), \
           "r"((r)[20]),"r"((r)[21]),"r"((r)[22]),"r"((r)[23]), \
           "r"((r)[24]),"r"((r)[25]),"r"((r)[26]),"r"((r)[27]), \
           "r"((r)[28]),"r"((r)[29]),"r"((r)[30]),"r"((r)[31]) \
        : "memory")

// SMEM descriptor: SW128, version=1, SBO=64, LBO=1
__device__ __forceinline__ uint64_t mk_desc(uint32_t base) {
    const uint64_t B =
        (uint64_t(2) << 61) | (uint64_t(1) << 46) | (uint64_t(64) << 32) | (uint64_t(1) << 16);
    return B | ((uint64_t)(base >> 4) & 0x3FFF);
}

// TS-mode cg1 kind::f16 MMA (A in TMEM, fp16 operands, fp32 acc)
__device__ __forceinline__ void mma_ts(uint32_t d, uint32_t a_tm, uint64_t b,
                                       uint32_t idesc, uint32_t acc) {
    asm volatile(
        "{\n\t.reg .pred p;\n\tsetp.ne.u32 p, %4, 0;\n\t"
        "tcgen05.mma.cta_group::1.kind::f16 [%0], [%1], %2, %3, {%5,%5,%5,%5}, p;\n\t}"
        :: "r"(d), "r"(a_tm), "l"(b), "r"(idesc), "r"(acc), "r"(0u) : "memory");
}
#endif  // TC_OK

// idesc: dtype=F32(1<<4), atype=FP16(0), btype=FP16(0), N=128, M=128
#define IDESC_H ((1u<<4)|((128u/8)<<17)|((128u/16)<<24))

// Blocked SW128 atom layout for a [128 rows, K cols] fp16 tile in smem.
__device__ __forceinline__ uint32_t lay128(int r, int c) {
    uint32_t off = ((uint32_t)(c >> 6) * 16u + (uint32_t)(r >> 3)) * 1024u
                 + (uint32_t)(r & 7) * 128u + (uint32_t)(c & 63) * 2u;
    return off ^ ((off >> 3) & 0x70u);
}
__device__ __forceinline__ uint32_t doff(int s) {
    return (uint32_t)(s >> 2) * 1024u + (uint32_t)(s & 3) * 2u;
}

// pack two fp32 -> fp16x2 (a = low element)
__device__ __forceinline__ uint32_t f2h2(float a, float b) {
    uint32_t r;
    asm("cvt.rn.f16x2.f32 %0, %1, %2;" : "=r"(r) : "f"(b), "f"(a));
    return r;
}

#if TC_OK
// W conv: fp32 [K,128] -> fp16 [N=128,K] blocked SW128 in smem (single plane).
template<int K>
__device__ __forceinline__ void conv_w(char* smem, const float* Wb, int off, int t) {
    #pragma unroll 2
    for (int i = t; i < (K / 2) * 32; i += 256) {
        int kp = i >> 5;
        int n4 = (i & 31) * 4;
        float4 v0 = *(const float4*)(Wb + (size_t)(2 * kp) * 128 + n4);
        float4 v1 = *(const float4*)(Wb + (size_t)(2 * kp + 1) * 128 + n4);
        const float* e0 = (const float*)&v0;
        const float* e1 = (const float*)&v1;
        #pragma unroll
        for (int j = 0; j < 4; j++)
            *(uint32_t*)(smem + off + lay128(n4 + j, 2 * kp)) = f2h2(e0[j], e1[j]);
    }
}

// single-plane MMA chain: D = A*W, K/16 steps
template<int K>
__device__ __forceinline__ void mma_chain(uint32_t d, uint32_t tmemA, uint64_t w) {
    constexpr int NS = K / 16;
    #pragma unroll
    for (int s = 0; s < NS; s++)
        mma_ts(d, tmemA + s * 8, w + doff(s), IDESC_H, s > 0);
}
#endif

// ---------------------------------------------------------------------------
// Fused QKV: X fp16 in; Q/K/V fp16 out.  Grid = 576. 256 threads, 2 CTAs/SM.
// TMEM: A[0,64) D[64,192). smem: 2x8KB stage + 3x32KB fp16 W = 113KB.
// ---------------------------------------------------------------------------
__global__ void __launch_bounds__(256, 2) qkv_ts(
    const __half* __restrict__ X,
    const float* __restrict__ Wq, const float* __restrict__ Wk,
    const float* __restrict__ Wv,
    __half* __restrict__ Qo, __half* __restrict__ Ko, __half* __restrict__ Vo)
{
    extern __shared__ char smem[];
    const int t = threadIdx.x;
    const int bz = blockIdx.x;
    const __half* Ab = X + (size_t)bz * 512 * 128;

#if TC_OK
    constexpr int OFF_STG = 1024;              // 2 x 8KB fp16 stage
    constexpr int OFF_W   = OFF_STG + 16384;   // 3 x 32KB fp16 W
    const uint32_t sb = smem_u32(smem);
    const int wid = t >> 5, lid = t & 31;

    if (t == 0) MBAR_INIT(sb + 8, 1);

    const float* Ws[3] = { Wq + (size_t)bz * 128 * 128,
                           Wk + (size_t)bz * 128 * 128,
                           Wv + (size_t)bz * 128 * 128 };
    #pragma unroll
    for (int w = 0; w < 3; w++)
        conv_w<128>(smem, Ws[w], OFF_W + w * 32768, t);

    __syncthreads();
    if (wid == 0) { TC_ALLOC(sb, 256); TC_RELINQ(); }
    __syncthreads();
    uint32_t tmem;
    asm volatile("ld.shared.b32 %0, [%1];" : "=r"(tmem) : "r"(sb));
    const uint32_t TM_A = tmem;        // 64 cols (fp16x2)
    const uint32_t D    = tmem + 64;   // 128 cols fp32

    __half* const Os[3] = { Qo + (size_t)bz * 512 * 128,
                            Ko + (size_t)bz * 512 * 128,
                            Vo + (size_t)bz * 512 * 128 };
    uint64_t wd[3];
    #pragma unroll
    for (int w = 0; w < 3; w++) wd[w] = mk_desc(sb + OFF_W + w * 32768);

    const int sub = wid & 3;
    const int h   = wid >> 2;
    const int row = sub * 32 + lid;
    const int c0  = h * 64;

    // stage chunk g: 128 rows x 32 halves (64B/row, 4 slots, swizzle (j+r)&3)
    auto stage_issue = [&](int g) {
        const int tile = g >> 2;
        const int c    = g & 3;
        const __half* At = Ab + (size_t)tile * 128 * 128 + c * 32;
        const uint32_t dstb = sb + OFF_STG + (uint32_t)(g & 1) * 8192u;
        #pragma unroll
        for (int i = t; i < 512; i += 256) {
            int r = i >> 2, j = i & 3;
            const __half* src = At + (size_t)r * 128 + j * 8;
            uint32_t dst = dstb + (uint32_t)(r * 64 + (((j + r) & 3) << 4));
            asm volatile("cp.async.cg.shared.global [%0], [%1], 16;"
                         :: "r"(dst), "l"(src));
        }
        CP_COMMIT();
    };

    stage_issue(0);
    int g = 0, p0 = 0;

    for (int tile = 0; tile < 4; tile++) {
        // ---- conv X tile -> TMEM A (fp16 passthrough) ----
        #pragma unroll
        for (int c = 0; c < 4; c++, g++) {
            if (g + 1 < 16) { stage_issue(g + 1); CP_WAIT1(); }
            else            { CP_WAIT0(); }
            __syncthreads();
            const char* sbuf = smem + OFF_STG + (g & 1) * 8192;
            uint32_t rr[8];
            #pragma unroll
            for (int jj = 0; jj < 2; jj++) {
                int j = h * 2 + jj;                      // distinct slots per h!
                uint4 hv = *(const uint4*)(sbuf + row * 64 + (((j + row) & 3) << 4));
                const uint32_t* hw = (const uint32_t*)&hv;
                #pragma unroll
                for (int m = 0; m < 4; m++) rr[jj * 4 + m] = hw[m];
            }
            TC_ST_X8(TM_A + c * 16 + h * 8, rr);
            TC_WAIT_ST();
            __syncthreads();
        }
        TC_FENCE_BEFORE();
        __syncthreads();

        // ---- 3 serial projections through D ----
        #pragma unroll
        for (int w = 0; w < 3; w++) {
            if (wid == 0) {
                FENCE_ASYNC();
                TC_FENCE_AFTER();
                if (elect_one()) { mma_chain<128>(D, TM_A, wd[w]); TC_COMMIT(sb + 8); }
            }
            mbar_wait(sb + 8, p0); p0 ^= 1;
            TC_FENCE_AFTER();
            {
                __half* cp = Os[w] + ((size_t)tile * 128 + row) * 128;
                #pragma unroll
                for (int cb = 0; cb < 2; cb++) {
                    const int cc = c0 + cb * 32;
                    uint32_t r[32];
                    TC_LD_X32(r, D + cc);
                    TC_WAIT_LD();
                    #pragma unroll
                    for (int q8 = 0; q8 < 8; q8++) {
                        uint2 hv;
                        hv.x = f2h2(__uint_as_float(r[q8*4+0]), __uint_as_float(r[q8*4+1]));
                        hv.y = f2h2(__uint_as_float(r[q8*4+2]), __uint_as_float(r[q8*4+3]));
                        *(uint2*)(cp + cc + q8 * 4) = hv;
                    }
                }
                TC_FENCE_BEFORE();
            }
            __syncthreads();   // D reads done before next MMA / A overwrite
        }
    }

    __syncthreads();
    if (t == 0) MBAR_INVAL(sb + 8);
    __syncthreads();
    if (wid == 0) TC_DEALLOC(tmem, 256);
#else
    const float* Wsrc[3] = { Wq + (size_t)bz*128*128, Wk + (size_t)bz*128*128,
                             Wv + (size_t)bz*128*128 };
    __half* Outs[3] = { Qo + (size_t)bz*512*128, Ko + (size_t)bz*512*128,
                        Vo + (size_t)bz*512*128 };
    for (int w = 0; w < 3; w++)
        for (int i = t; i < 512 * 128; i += 256) {
            int r = i >> 7, c = i & 127;
            float s = 0.f;
            for (int k = 0; k < 128; k++)
                s += __half2float(Ab[(size_t)r * 128 + k]) * Wsrc[w][(size_t)k * 128 + c];
            Outs[w][i] = __float2half(s);
        }
#endif
}

// ---------------------------------------------------------------------------
// Fused 2-stage GEMM: H = epi1(A@W1 [+b1][relu][+Res fp16]);
//                     Out fp16 = epi2(H@W2 [+b2][relu]).
// AHALF: A fp16 (else fp32). TMEM: A[0,64) H[64,128) D[128,256). 2 CTAs/SM.
// ---------------------------------------------------------------------------
template<int K1, bool BIAS1, bool RELU1, bool RES1, bool BIAS2, bool RELU2,
         bool AHALF>
__global__ void __launch_bounds__(256, 2) gemm2_ts(
    const void* __restrict__ Av,
    const float* __restrict__ W1, const float* __restrict__ b1,
    const void* __restrict__ Resv,
    const float* __restrict__ W2, const float* __restrict__ b2,
    __half* __restrict__ Out)
{
    extern __shared__ char smem[];
    const int t = threadIdx.x;
    const int bz = blockIdx.x;
    const __half* Rb = RES1 ? (const __half*)Resv + (size_t)bz * 512 * 128 : nullptr;
    __half*       Ob = Out + (size_t)bz * 512 * 128;

#if TC_OK
    constexpr int STGBUF  = AHALF ? 8192 : 16384;
    constexpr int W1BYTES = (K1 >= 128) ? 32768 : 16384;
    constexpr int OFF_STG = 2048;
    constexpr int OFF_W1  = OFF_STG + 2 * STGBUF;
    constexpr int OFF_W2  = OFF_W1 + W1BYTES;
    constexpr int NCHK1 = K1 / 32;
    constexpr int NG = 4 * NCHK1;

    const uint32_t sb = smem_u32(smem);
    const int wid = t >> 5, lid = t & 31;
    float* bias1_s = (float*)(smem + 64);
    float* bias2_s = (float*)(smem + 576);

    if (t == 0) MBAR_INIT(sb + 8, 1);
    conv_w<K1 >(smem, W1 + (size_t)bz * K1 * 128, OFF_W1, t);
    conv_w<128>(smem, W2 + (size_t)bz * 128 * 128, OFF_W2, t);
    if (BIAS1 && t < 128) bias1_s[t] = b1[(size_t)bz * 128 + t];
    if (BIAS2 && t < 128) bias2_s[t] = b2[(size_t)bz * 128 + t];

    __syncthreads();
    if (wid == 0) { TC_ALLOC(sb, 256); TC_RELINQ(); }
    __syncthreads();
    uint32_t tmem;
    asm volatile("ld.shared.b32 %0, [%1];" : "=r"(tmem) : "r"(sb));
    const uint32_t TM_A = tmem;
    const uint32_t TM_H = tmem + 64;
    const uint32_t D    = tmem + 128;

    const uint64_t w1d = mk_desc(sb + OFF_W1);
    const uint64_t w2d = mk_desc(sb + OFF_W2);

    const int sub = wid & 3;
    const int h   = wid >> 2;
    const int row = sub * 32 + lid;
    const int c0  = h * 64;

    int g = 0, p0 = 0;

    auto stage_issue = [&](int gg) {
        const int tile = gg / NCHK1;
        const int c    = gg - tile * NCHK1;
        if (AHALF) {
            const __half* At = (const __half*)Av
                + (size_t)bz * 512 * K1 + (size_t)tile * 128 * K1 + c * 32;
            const uint32_t dstb = sb + OFF_STG + (uint32_t)(gg & 1) * 8192u;
            #pragma unroll
            for (int i = t; i < 512; i += 256) {
                int r = i >> 2, j = i & 3;
                const __half* src = At + (size_t)r * K1 + j * 8;
                uint32_t dst = dstb + (uint32_t)(r * 64 + (((j + r) & 3) << 4));
                asm volatile("cp.async.cg.shared.global [%0], [%1], 16;"
                             :: "r"(dst), "l"(src));
            }
        } else {
            const float* At = (const float*)Av
                + (size_t)bz * 512 * K1 + (size_t)tile * 128 * K1 + c * 32;
            const uint32_t dstb = sb + OFF_STG + (uint32_t)(gg & 1) * 16384u;
            #pragma unroll
            for (int i = t; i < 1024; i += 256) {
                int r = i >> 3, j = i & 7;
                const float* src = At + (size_t)r * K1 + j * 4;
                uint32_t dst = dstb + (uint32_t)(r * 128 + (((j + r) & 7) << 4));
                asm volatile("cp.async.cg.shared.global [%0], [%1], 16;"
                             :: "r"(dst), "l"(src));
            }
        }
        CP_COMMIT();
    };

    auto convA = [&]() {
        #pragma unroll
        for (int c = 0; c < NCHK1; c++, g++) {
            if (g + 1 < NG) { stage_issue(g + 1); CP_WAIT1(); }
            else            { CP_WAIT0(); }
            __syncthreads();
            uint32_t rr[8];
            if (AHALF) {
                const char* sbuf = smem + OFF_STG + (g & 1) * 8192;
                #pragma unroll
                for (int jj = 0; jj < 2; jj++) {
                    int j = h * 2 + jj;
                    uint4 hv = *(const uint4*)(sbuf + row * 64 + (((j + row) & 3) << 4));
                    const uint32_t* hw = (const uint32_t*)&hv;
                    #pragma unroll
                    for (int m = 0; m < 4; m++) rr[jj * 4 + m] = hw[m];
                }
            } else {
                const char* sbuf = smem + OFF_STG + (g & 1) * 16384;
                #pragma unroll
                for (int jj = 0; jj < 4; jj++) {
                    int j = h * 4 + jj;
                    float4 v = *(const float4*)(sbuf + row * 128 + (((j + row) & 7) << 4));
                    rr[jj * 2 + 0] = f2h2(v.x, v.y);
                    rr[jj * 2 + 1] = f2h2(v.z, v.w);
                }
            }
            TC_ST_X8(TM_A + c * 16 + h * 8, rr);
            TC_WAIT_ST();
            __syncthreads();
        }
        TC_FENCE_BEFORE();
        __syncthreads();
    };

    stage_issue(0);

    for (int tile = 0; tile < 4; tile++) {
        convA();
        // ---- MMA1 -> D ----
        if (wid == 0) {
            FENCE_ASYNC();
            TC_FENCE_AFTER();
            if (elect_one()) { mma_chain<K1>(D, TM_A, w1d); TC_COMMIT(sb + 8); }
        }
        mbar_wait(sb + 8, p0); p0 ^= 1;
        TC_FENCE_AFTER();

        // ---- epi1: D (+res/b1/relu) -> fp16 -> TM_H ----
        {
            float d[64];
            #pragma unroll
            for (int cb = 0; cb < 2; cb++) {
                uint32_t r[32];
                TC_LD_X32(r, D + c0 + cb * 32);
                TC_WAIT_LD();
                #pragma unroll
                for (int q = 0; q < 32; q++) d[cb * 32 + q] = __uint_as_float(r[q]);
            }
            if (RES1) {
                const __half* rp = Rb + ((size_t)tile * 128 + row) * 128 + c0;
                #pragma unroll
                for (int q8 = 0; q8 < 8; q8++) {
                    uint4 hv = *(const uint4*)(rp + q8 * 8);
                    const uint32_t* hw = (const uint32_t*)&hv;
                    #pragma unroll
                    for (int m = 0; m < 4; m++) {
                        float2 f = __half22float2(*(const __half2*)&hw[m]);
                        d[q8*8 + m*2 + 0] += f.x;
                        d[q8*8 + m*2 + 1] += f.y;
                    }
                }
            }
            if (BIAS1) {
                #pragma unroll
                for (int q = 0; q < 64; q++) d[q] += bias1_s[c0 + q];
            }
            if (RELU1) {
                #pragma unroll
                for (int q = 0; q < 64; q++) d[q] = fmaxf(d[q], 0.f);
            }
            uint32_t hh[32];
            #pragma unroll
            for (int j = 0; j < 32; j++) hh[j] = f2h2(d[2*j], d[2*j+1]);
            TC_ST_X32(TM_H + h * 32, hh);
            TC_WAIT_ST();
            TC_FENCE_BEFORE();
        }
        __syncthreads();   // D reads done, H complete

        // ---- MMA2 -> D ----
        if (wid == 0) {
            TC_FENCE_AFTER();
            if (elect_one()) { mma_chain<128>(D, TM_H, w2d); TC_COMMIT(sb + 8); }
        }
        mbar_wait(sb + 8, p0); p0 ^= 1;
        TC_FENCE_AFTER();

        // ---- epi2: D (+b2/relu) -> fp16 out ----
        {
            __half* cp = Ob + ((size_t)tile * 128 + row) * 128;
            #pragma unroll
            for (int cb = 0; cb < 2; cb++) {
                const int cc = c0 + cb * 32;
                uint32_t r[32];
                TC_LD_X32(r, D + cc);
                TC_WAIT_LD();
                #pragma unroll
                for (int q8 = 0; q8 < 8; q8++) {
                    float4 v = make_float4(
                        __uint_as_float(r[q8*4+0]), __uint_as_float(r[q8*4+1]),
                        __uint_as_float(r[q8*4+2]), __uint_as_float(r[q8*4+3]));
                    if (BIAS2) {
                        v.x += bias2_s[cc + q8*4+0]; v.y += bias2_s[cc + q8*4+1];
                        v.z += bias2_s[cc + q8*4+2]; v.w += bias2_s[cc + q8*4+3];
                    }
                    if (RELU2) {
                        v.x = fmaxf(v.x, 0.f); v.y = fmaxf(v.y, 0.f);
                        v.z = fmaxf(v.z, 0.f); v.w = fmaxf(v.w, 0.f);
                    }
                    uint2 hv;
                    hv.x = f2h2(v.x, v.y);
                    hv.y = f2h2(v.z, v.w);
                    *(uint2*)(cp + cc + q8 * 4) = hv;
                }
            }
            TC_FENCE_BEFORE();
        }
        __syncthreads();   // A/H/D free for next tile
    }

    __syncthreads();
    if (t == 0) MBAR_INVAL(sb + 8);
    __syncthreads();
    if (wid == 0) TC_DEALLOC(tmem, 256);
#else
    float* Hs = (float*)(smem + 2048);   // 128 x 132
    const float* W1b = W1 + (size_t)bz * K1 * 128;
    const float* W2b = W2 + (size_t)bz * 128 * 128;
    for (int tile = 0; tile < 4; tile++) {
        for (int i = t; i < 128 * 128; i += 256) {
            int r = i >> 7, c = i & 127;
            float s = 0.f;
            for (int k = 0; k < K1; k++) {
                float av = AHALF
                    ? __half2float(((const __half*)Av)[(size_t)bz*512*K1
                        + ((size_t)tile*128 + r) * K1 + k])
                    : ((const float*)Av)[(size_t)bz*512*K1
                        + ((size_t)tile*128 + r) * K1 + k];
                s += av * W1b[(size_t)k * 128 + c];
            }
            if (BIAS1) s += b1[(size_t)bz * 128 + c];
            if (RES1)  s += __half2float(Rb[((size_t)tile * 128 + r) * 128 + c]);
            if (RELU1) s = fmaxf(s, 0.f);
            Hs[r * 132 + c] = s;
        }
        __syncthreads();
        for (int i = t; i < 128 * 128; i += 256) {
            int r = i >> 7, c = i & 127;
            float s = 0.f;
            for (int k = 0; k < 128; k++)
                s += Hs[r * 132 + k] * W2b[(size_t)k * 128 + c];
            if (BIAS2) s += b2[(size_t)bz * 128 + c];
            if (RELU2) s = fmaxf(s, 0.f);
            Ob[((size_t)tile * 128 + r) * 128 + c] = __float2half(s);
        }
        __syncthreads();
    }
#endif
}

// ---------------------------------------------------------------------------
// Single GEMM (predictor): C fp32 = relu(A fp32 @ W + b). Grid = 64.
// ---------------------------------------------------------------------------
template<int K, bool RELU, bool BIAS>
__global__ void __launch_bounds__(256, 2) gemm_ts(
    const float* __restrict__ A,
    const float* __restrict__ W,
    const float* __restrict__ bias,
    float* __restrict__ C)
{
    extern __shared__ char smem[];
    const int t = threadIdx.x;
    const int bz = blockIdx.x;
    const float* Ab = A + (size_t)bz * 512 * K;
    const float* Wb = W + (size_t)bz * K * 128;
    float*       Cb = C + (size_t)bz * 512 * 128;

#if TC_OK
    constexpr int OFF_STG = 1024;              // 2 x 16KB fp32 stage
    constexpr int OFF_W   = OFF_STG + 32768;
    constexpr int NCHK = K / 32;
    constexpr int NG   = 4 * NCHK;

    const uint32_t sb = smem_u32(smem);
    const int wid = t >> 5, lid = t & 31;
    float* bias_s = (float*)(smem + 32);

    if (t == 0) MBAR_INIT(sb + 8, 1);
    conv_w<K>(smem, Wb, OFF_W, t);
    if (BIAS && t < 128) bias_s[t] = bias[(size_t)bz * 128 + t];
    __syncthreads();
    if (wid == 0) { TC_ALLOC(sb, 256); TC_RELINQ(); }
    __syncthreads();
    uint32_t tmem;
    asm volatile("ld.shared.b32 %0, [%1];" : "=r"(tmem) : "r"(sb));
    const uint32_t TM_A = tmem;
    const uint32_t D    = tmem + 64;

    const uint64_t wdsc = mk_desc(sb + OFF_W);
    const int sub = wid & 3;
    const int h   = wid >> 2;
    const int row = sub * 32 + lid;
    const int c0  = h * 64;

    auto stage_issue = [&](int g) {
        const int tile = g / NCHK;
        const int c    = g - tile * NCHK;
        const float* At = Ab + (size_t)tile * 128 * K + c * 32;
        const uint32_t dstb = sb + OFF_STG + (uint32_t)(g & 1) * 16384u;
        #pragma unroll
        for (int i = t; i < 1024; i += 256) {
            int r = i >> 3, j = i & 7;
            const float* src = At + (size_t)r * K + j * 4;
            uint32_t dst = dstb + (uint32_t)(r * 128 + (((j + r) & 7) << 4));
            asm volatile("cp.async.cg.shared.global [%0], [%1], 16;"
                         :: "r"(dst), "l"(src));
        }
        CP_COMMIT();
    };

    stage_issue(0);
    int g = 0, parity = 0;
    for (int tile = 0; tile < 4; tile++) {
        #pragma unroll
        for (int c = 0; c < NCHK; c++, g++) {
            if (g + 1 < NG) { stage_issue(g + 1); CP_WAIT1(); }
            else            { CP_WAIT0(); }
            __syncthreads();
            const char* sbuf = smem + OFF_STG + (g & 1) * 16384;
            uint32_t rr[8];
            #pragma unroll
            for (int jj = 0; jj < 4; jj++) {
                int j = h * 4 + jj;
                float4 v = *(const float4*)(sbuf + row * 128 + (((j + row) & 7) << 4));
                rr[jj * 2 + 0] = f2h2(v.x, v.y);
                rr[jj * 2 + 1] = f2h2(v.z, v.w);
            }
            TC_ST_X8(TM_A + c * 16 + h * 8, rr);
            TC_WAIT_ST();
            __syncthreads();
        }
        TC_FENCE_BEFORE();
        __syncthreads();
        if (wid == 0) {
            FENCE_ASYNC();
            TC_FENCE_AFTER();
            if (elect_one()) { mma_chain<K>(D, TM_A, wdsc); TC_COMMIT(sb + 8); }
        }
        mbar_wait(sb + 8, parity); parity ^= 1;
        TC_FENCE_AFTER();
        {
            float* cp = Cb + ((size_t)tile * 128 + row) * 128;
            #pragma unroll
            for (int cb = 0; cb < 2; cb++) {
                const int cc = c0 + cb * 32;
                uint32_t r[32];
                TC_LD_X32(r, D + cc);
                TC_WAIT_LD();
                #pragma unroll
                for (int q8 = 0; q8 < 8; q8++) {
                    float4 v = make_float4(
                        __uint_as_float(r[q8*4+0]), __uint_as_float(r[q8*4+1]),
                        __uint_as_float(r[q8*4+2]), __uint_as_float(r[q8*4+3]));
                    if (BIAS) {
                        v.x += bias_s[cc+q8*4+0]; v.y += bias_s[cc+q8*4+1];
                        v.z += bias_s[cc+q8*4+2]; v.w += bias_s[cc+q8*4+3];
                    }
                    if (RELU) {
                        v.x = fmaxf(v.x, 0.f); v.y = fmaxf(v.y, 0.f);
                        v.z = fmaxf(v.z, 0.f); v.w = fmaxf(v.w, 0.f);
                    }
                    *(float4*)(cp + cc + q8 * 4) = v;
                }
            }
            TC_FENCE_BEFORE();
        }
        __syncthreads();
    }
    __syncthreads();
    if (t == 0) MBAR_INVAL(sb + 8);
    __syncthreads();
    if (wid == 0) TC_DEALLOC(tmem, 256);
#else
    for (int i = t; i < 512 * 128; i += 256) {
        int r = i >> 7, c = i & 127;
        float s = 0.f;
        for (int k = 0; k < K; k++)
            s += Ab[(size_t)r * K + k] * Wb[(size_t)k * 128 + c];
        if (BIAS) s += bias[(size_t)bz * 128 + c];
        if (RELU) s = fmaxf(s, 0.f);
        Cb[(size_t)r * 128 + c] = s;
    }
#endif
}

// ---------------------------------------------------------------------------
// Attention core: Q,K,V fp16 in (16B loads); T fp16 out. 256 threads, 2 batches.
// ---------------------------------------------------------------------------
__global__ void __launch_bounds__(256) attn_kernel(
    const __half* __restrict__ Q, const __half* __restrict__ Kk,
    const __half* __restrict__ V, __half* __restrict__ T)
{
    const int blk = blockIdx.x;
    const int ef  = blk >> 8;
    const int bp  = (blk & 255) << 1;

    __shared__ float qs[2][NO][132];
    __shared__ float ks[2][NO][132];
    __shared__ float vs[2][NO][132];
    __shared__ float lg[2][4][NO][12];

    const int t  = threadIdx.x;
    const int g  = t >> 7;
    const int tl = t & 127;
    const int b  = bp + g;

    for (int idx = tl; idx < NO * 16; idx += 128) {
        int o  = idx >> 4;
        int c8 = (idx & 15) * 8;
        size_t ga = ((size_t)(ef * NO + o) * NB + b) * 128 + c8;
        uint4 qv = *(const uint4*)(Q + ga);
        uint4 kv = *(const uint4*)(Kk + ga);
        uint4 vv = *(const uint4*)(V + ga);
        const uint32_t* qw = (const uint32_t*)&qv;
        const uint32_t* kw = (const uint32_t*)&kv;
        const uint32_t* vw = (const uint32_t*)&vv;
        #pragma unroll
        for (int m = 0; m < 4; m++) {
            float2 fq = __half22float2(*(const __half2*)&qw[m]);
            float2 fk = __half22float2(*(const __half2*)&kw[m]);
            float2 fv = __half22float2(*(const __half2*)&vw[m]);
            qs[g][o][c8 + 2*m + 0] = fq.x; qs[g][o][c8 + 2*m + 1] = fq.y;
            ks[g][o][c8 + 2*m + 0] = fk.x; ks[g][o][c8 + 2*m + 1] = fk.y;
            vs[g][o][c8 + 2*m + 0] = fv.x; vs[g][o][c8 + 2*m + 1] = fv.y;
        }
    }
    __syncthreads();

    const float scale = 0.17677669529663687f;
    for (int e = tl; e < 4 * NO * NO; e += 128) {
        int h   = e / (NO * NO);
        int rem = e - h * NO * NO;
        int i   = rem / NO;
        int j   = rem - i * NO;
        float s = 0.f;
        #pragma unroll
        for (int d = 0; d < 32; d++) s += qs[g][i][h * 32 + d] * ks[g][j][h * 32 + d];
        lg[g][h][i][j] = s * scale;
    }
    __syncthreads();

    if (tl < 4 * NO) {
        int h = tl / NO, i = tl - (tl / NO) * NO;
        float mx = -1e30f;
        #pragma unroll
        for (int j = 0; j < NO; j++) mx = fmaxf(mx, lg[g][h][i][j]);
        float ex[NO]; float s = 0.f;
        #pragma unroll
        for (int j = 0; j < NO; j++) { ex[j] = __expf(lg[g][h][i][j] - mx); s += ex[j]; }
        float inv = 1.f / s;
        #pragma unroll
        for (int j = 0; j < NO; j++) lg[g][h][i][j] = ex[j] * inv;
    }
    __syncthreads();

    const int c = tl, h = c >> 5;
    #pragma unroll
    for (int i = 0; i < NO; i++) {
        float s = 0.f;
        #pragma unroll
        for (int j = 0; j < NO; j++) s += lg[g][h][i][j] * vs[g][j][c];
        T[((size_t)(ef * NO + i) * NB + b) * 128 + c] = __float2half(s);
    }
}

__global__ void __launch_bounds__(256) pool_kernel(
    const __half* __restrict__ Hin, float* __restrict__ P)
{
    int idx = blockIdx.x * 256 + threadIdx.x;
    if (idx >= NEF * NB * NDH) return;
    int c = idx & 127, b = (idx >> 7) & 511, ef = idx >> 16;
    float s = 0.f;
    #pragma unroll
    for (int o = 0; o < NO; o++)
        s += __half2float(Hin[((size_t)(ef * NO + o) * NB + b) * 128 + c]);
    P[idx] = s * (1.f / 9.f);
}

__global__ void __launch_bounds__(256) final_kernel(
    const float* __restrict__ A, const float* __restrict__ W,
    const float* __restrict__ bias, float* __restrict__ Out)
{
    const int mt = blockIdx.x;
    const int ef = blockIdx.y;
    __shared__ float As[32][128];
    __shared__ float Ws[128][NFINAL];
    __shared__ float bs[NFINAL];
    const int t = threadIdx.x;
    const float* Ab = A + ((size_t)ef * NB + mt * 32) * 128;
    for (int i = t; i < 32 * 128 / 4; i += 256)
        ((float4*)&As[0][0])[i] = ((const float4*)Ab)[i];
    for (int i = t; i < 128 * NFINAL; i += 256)
        Ws[i / NFINAL][i % NFINAL] = W[(size_t)ef * 128 * NFINAL + i];
    if (t < NFINAL) bs[t] = bias[ef * NFINAL + t];
    __syncthreads();
    for (int idx = t; idx < 32 * NFINAL; idx += 256) {
        int r = idx / NFINAL, j = idx - r * NFINAL;
        float s = bs[j];
        #pragma unroll 16
        for (int k = 0; k < 128; k++) s += As[r][k] * Ws[k][j];
        Out[((size_t)ef * NB + mt * 32 + r) * NFINAL + j] = s;
    }
}

// ---------------------------------------------------------------------------
extern "C" void kernel_launch(void* const* d_in, const int* in_sizes, int n_in,
                              void* d_out, int out_size)
{
    const float* x   = (const float*)d_in[0];
    const float* fw1 = (const float*)d_in[1];
    const float* fb1 = (const float*)d_in[2];
    const float* fw2 = (const float*)d_in[3];
    const float* fb2 = (const float*)d_in[4];
    const float* aw[2][5];
    const float* apb[2];
    for (int i = 0; i < 2; i++) {
        for (int n = 0; n < 5; n++) aw[i][n] = (const float*)d_in[5 + i * 6 + n];
        apb[i] = (const float*)d_in[5 + i * 6 + 5];
    }
    const float* pw1 = (const float*)d_in[17];
    const float* pb1 = (const float*)d_in[18];
    const float* pw2 = (const float*)d_in[19];
    const float* pb2 = (const float*)d_in[20];
    float* out = (float*)d_out;

    __half *H1, *H2, *Q, *K, *V, *T;
    float *PO, *P;
    cudaGetSymbolAddress((void**)&H1, g_h1);
    cudaGetSymbolAddress((void**)&H2, g_h2);
    cudaGetSymbolAddress((void**)&Q,  g_q);
    cudaGetSymbolAddress((void**)&K,  g_k);
    cudaGetSymbolAddress((void**)&V,  g_v);
    cudaGetSymbolAddress((void**)&T,  g_t);
    cudaGetSymbolAddress((void**)&PO, g_po);
    cudaGetSymbolAddress((void**)&P,  g_p);

    const int SMQKV = 1024 + 16384 + 3 * 32768;          // 115,712
    const int SMF12 = 2048 + 2 * 16384 + 16384 + 32768;  // 83,968  (K1=32, A fp32)
    const int SMWP  = 2048 + 2 * 8192 + 2 * 32768;       // 83,968  (K1=128, A fp16)
    const int SMPRD = 1024 + 32768 + 32768;              // 66,560

    cudaFuncSetAttribute(qkv_ts, cudaFuncAttributeMaxDynamicSharedMemorySize, SMQKV);
    cudaFuncSetAttribute(
        gemm2_ts<32, true, true, false, true, true, false>,
        cudaFuncAttributeMaxDynamicSharedMemorySize, SMF12);
    cudaFuncSetAttribute(
        gemm2_ts<128, false, false, true, true, true, true>,
        cudaFuncAttributeMaxDynamicSharedMemorySize, SMWP);
    cudaFuncSetAttribute(gemm_ts<128, true, true>,
        cudaFuncAttributeMaxDynamicSharedMemorySize, SMPRD);

    // fused feature_fc (fc1 + fc2): x fp32 -> H2 fp16
    gemm2_ts<32, true, true, false, true, true, false><<<NCH, 256, SMF12>>>(
        x, fw1, fb1, nullptr, fw2, fb2, H2);

    // two ChannelMHA blocks (all intermediates fp16)
    const __half* X = H2;
    __half* Y = H1;
    for (int a = 0; a < 2; a++) {
        qkv_ts<<<NCH, 256, SMQKV>>>(X, aw[a][0], aw[a][1], aw[a][2], Q, K, V);
        attn_kernel<<<NEF * NB / 2, 256>>>(Q, K, V, T);
        // fused: Y = relu((T@wo + X) @ pw + pb)
        gemm2_ts<128, false, false, true, true, true, true><<<NCH, 256, SMWP>>>(
            T, aw[a][3], nullptr, X, aw[a][4], apb[a], Y);
        const __half* nX = Y;
        Y = (a == 0) ? H2 : H1;
        X = nX;
    }
    // X == H2 after the loop

    pool_kernel<<<(NEF * NB * NDH + 255) / 256, 256>>>(X, PO);
    gemm_ts<128, true, true><<<NEF, 256, SMPRD>>>(PO, pw1, pb1, P);
    final_kernel<<<dim3(16, NEF), 256>>>(P, pw2, pb2, out);
}